// round 13
// baseline (speedup 1.0000x reference)
#include <cuda_runtime.h>
#include <cuda_bf16.h>

typedef unsigned long long ull;
typedef unsigned int u32;

// ---------------------------------------------------------------------------
// Problem constants
// ---------------------------------------------------------------------------
#define Bn      1024
#define Tt      34
#define E       128
#define TWO_E   256
#define L0N     (Bn*Tt*8)    // 278528
#define L1N     (Bn*Tt*4)    // 139264
#define L2N     (Bn*Tt*2)    // 69632
#define L3N     (Bn*Tt)      // 34816
#define LFN     (Bn*9)       // 9216
#define LBASE0  0
#define LBASE1  (LBASE0 + 4*L0N)
#define LBASE2  (LBASE1 + 4*L1N)
#define LBASE3  (LBASE2 + 4*L2N)
#define LBASE4  (LBASE3 + 4*L3N)
#define LTOTAL  (LBASE4 + 3*LFN)

// ---- nf HMMA kernel geometry ----------------------------------------------
// M=64 rows/block, 8 warps (wm = wid>>2, wn = wid&3), 2 blocks/SM.
// A (X then H overlay) bf16 hi/lo, row stride 528B (16B-aligned).
// B: single chunk buffer (32 k), [n][k] stride 80B (16B-aligned!), staged
// from pre-converted bf16 hi/lo global weights.
#define AS_HI   0
#define AS_LO   33792                  // 64*528
#define BB_HI   67584
#define BB_LO   (BB_HI + 20480)        // 88064   (256*80)
#define SN_O    (BB_LO + 20480)        // 108544
#define NF_SMEM (SN_O + 256)           // 108800  (x2 = 217600 <= 228KB/SM)

// ---- lf scalar kernel geometry (unchanged, ~3% of FLOPs) -------------------
#define TMLF    32
#define XSTR    36
#define LF_XT_OFF   0
#define LF_HT_OFF   36864
#define LF_WS_OFF   (36864 + 73728)
#define LF_SN_OFF   (LF_WS_OFF + 32768)
#define LF_SMEM     (LF_SN_OFF + 128)

// ---------------------------------------------------------------------------
// PTX helpers: ldmatrix + mma (baseline PTX, legal at compute_103)
// ---------------------------------------------------------------------------
__device__ __forceinline__ u32 smem_u32(const void* p) {
    u32 a;
    asm("{ .reg .u64 t; cvta.to.shared.u64 t, %1; cvt.u32.u64 %0, t; }"
        : "=r"(a) : "l"(p));
    return a;
}

#define LDMX4(r, addr) \
    asm volatile("ldmatrix.sync.aligned.m8n8.x4.shared.b16 {%0,%1,%2,%3}, [%4];" \
        : "=r"((r)[0]), "=r"((r)[1]), "=r"((r)[2]), "=r"((r)[3]) : "r"(addr))

#define MMA_BF16(d, a, b0, b1) \
    asm volatile("mma.sync.aligned.m16n8k16.row.col.f32.bf16.bf16.f32 " \
        "{%0,%1,%2,%3}, {%4,%5,%6,%7}, {%8,%9}, {%0,%1,%2,%3};" \
        : "+f"((d)[0]), "+f"((d)[1]), "+f"((d)[2]), "+f"((d)[3]) \
        : "r"((a)[0]), "r"((a)[1]), "r"((a)[2]), "r"((a)[3]), \
          "r"(b0), "r"(b1))

// split fp32 pair -> packed bf16 hi pair + lo pair (x ~= hi + lo to ~2^-17)
__device__ __forceinline__ void split2(float v0, float v1, u32& hp, u32& lp) {
    __nv_bfloat16 h0 = __float2bfloat16_rn(v0);
    __nv_bfloat16 h1 = __float2bfloat16_rn(v1);
    float r0 = v0 - __bfloat162float(h0);
    float r1 = v1 - __bfloat162float(h1);
    __nv_bfloat16 l0 = __float2bfloat16_rn(r0);
    __nv_bfloat16 l1 = __float2bfloat16_rn(r1);
    hp = (u32)__bfloat16_as_ushort(h0) | ((u32)__bfloat16_as_ushort(h1) << 16);
    lp = (u32)__bfloat16_as_ushort(l0) | ((u32)__bfloat16_as_ushort(l1) << 16);
}

// ---------------------------------------------------------------------------
// Packed fp32x2 helpers (lf scalar kernel)
// ---------------------------------------------------------------------------
__device__ __forceinline__ void fma2(ull& d, ull a, ull b) {
    asm("fma.rn.f32x2 %0, %1, %2, %0;" : "+l"(d) : "l"(a), "l"(b));
}
__device__ __forceinline__ ull pack_dup(float w) {
    ull r; unsigned wi = __float_as_uint(w);
    asm("mov.b64 %0, {%1, %2};" : "=l"(r) : "r"(wi), "r"(wi));
    return r;
}
__device__ __forceinline__ float2 unpack2(ull v) {
    unsigned lo, hi;
    asm("mov.b64 {%0, %1}, %2;" : "=r"(lo), "=r"(hi) : "l"(v));
    float2 f; f.x = __uint_as_float(lo); f.y = __uint_as_float(hi);
    return f;
}

// ---------------------------------------------------------------------------
// Scratch (device globals; no allocation allowed)
// ---------------------------------------------------------------------------
__device__ float g_buf0[(size_t)L0N * E];
__device__ float g_buf1[(size_t)L1N * E];
__device__ float g_roots[(size_t)L3N * E];
__device__ float g_stmt[(size_t)LFN * E];
__device__ int   g_counts[20];
__device__ int   g_lists[LTOTAL];
// pre-converted weights: hi/lo packed bf16 pairs, layout [e][n][kp]
__device__ u32   g_w1h[4 * 256 * 128], g_w1l[4 * 256 * 128];
__device__ u32   g_w2h[4 * 128 * 128], g_w2l[4 * 128 * 128];

__global__ void zero_counts_kernel() {
    if (threadIdx.x < 20) g_counts[threadIdx.x] = 0;
}

// ---------------------------------------------------------------------------
// Weight pre-conversion: fp32 -> packed bf16 hi/lo pairs, k-pair major.
// ---------------------------------------------------------------------------
__global__ void prep_w_kernel(const float* __restrict__ W1,
                              const float* __restrict__ W2) {
    int t = blockIdx.x * 256 + threadIdx.x;
    if (t < 4 * 256 * 128) {
        int e = t >> 15, r = t & 32767, n = r >> 7, kp = r & 127;
        const float* W = W1 + (size_t)e * TWO_E * TWO_E;
        float w0 = W[(size_t)(2 * kp) * TWO_E + n];
        float w1 = W[(size_t)(2 * kp + 1) * TWO_E + n];
        u32 hp, lp; split2(w0, w1, hp, lp);
        g_w1h[t] = hp; g_w1l[t] = lp;
    } else {
        t -= 4 * 256 * 128;
        int e = t >> 14, r = t & 16383, n = r >> 7, kp = r & 127;
        const float* W = W2 + (size_t)e * TWO_E * E;
        float w0 = W[(size_t)(2 * kp) * E + n];
        float w1 = W[(size_t)(2 * kp + 1) * E + n];
        u32 hp, lp; split2(w0, w1, hp, lp);
        g_w2h[t] = hp; g_w2l[t] = lp;
    }
}

// ---------------------------------------------------------------------------
// Expert compaction (warp-aggregated atomics)
// ---------------------------------------------------------------------------
__global__ void compact_kernel(const int* __restrict__ nf_ids,
                               const int* __restrict__ lf_ids) {
    int gid = blockIdx.x * 256 + threadIdx.x;
    int slot, store_base, nid;
    if (gid < L0N) {
        nid = gid;
        int bt = nid >> 3, j = nid & 7;
        int id = nf_ids[bt * 15 + j];
        slot = id;               store_base = LBASE0 + id * L0N;
    } else if (gid < L0N + L1N) {
        nid = gid - L0N;
        int bt = nid >> 2, j = nid & 3;
        int id = nf_ids[bt * 15 + 8 + j];
        slot = 4 + id;           store_base = LBASE1 + id * L1N;
    } else if (gid < L0N + L1N + L2N) {
        nid = gid - (L0N + L1N);
        int bt = nid >> 1, j = nid & 1;
        int id = nf_ids[bt * 15 + 12 + j];
        slot = 8 + id;           store_base = LBASE2 + id * L2N;
    } else if (gid < L0N + L1N + L2N + L3N) {
        nid = gid - (L0N + L1N + L2N);
        int id = nf_ids[nid * 15 + 14];
        slot = 12 + id;          store_base = LBASE3 + id * L3N;
    } else {
        nid = gid - (L0N + L1N + L2N + L3N);
        int id = lf_ids[nid];
        slot = 16 + id;          store_base = LBASE4 + id * LFN;
    }
    unsigned mm = __match_any_sync(0xFFFFFFFFu, slot);
    int lane   = threadIdx.x & 31;
    int leader = __ffs(mm) - 1;
    int rank   = __popc(mm & ((1u << lane) - 1));
    int base   = 0;
    if (lane == leader) base = atomicAdd(&g_counts[slot], __popc(mm));
    base = __shfl_sync(0xFFFFFFFFu, base, leader);
    g_lists[store_base + base + rank] = nid;
}

// ---------------------------------------------------------------------------
// nf expert MLP on HMMA (split-bf16, fp32 accum), 2 blocks/SM.
// ---------------------------------------------------------------------------
__global__ void __launch_bounds__(256, 2)
nf_mma_kernel(int lvl,
              const int* __restrict__ leaf_idx,
              const float* __restrict__ ent_emb,
              const float* __restrict__ b1, const float* __restrict__ b2) {
    extern __shared__ char smem[];
    u32 sb = smem_u32(smem);
    int tid = threadIdx.x, wid = tid >> 5, lane = tid & 31;
    int wm = wid >> 2, wn = wid & 3;

    int stride, list_base, counts_off;
    const float* in; float* outp;
    switch (lvl) {
        case 0:  stride = L0N; list_base = LBASE0; counts_off = 0;  in = 0;      outp = g_buf0;  break;
        case 1:  stride = L1N; list_base = LBASE1; counts_off = 4;  in = g_buf0; outp = g_buf1;  break;
        case 2:  stride = L2N; list_base = LBASE2; counts_off = 8;  in = g_buf1; outp = g_buf0;  break;
        default: stride = L3N; list_base = LBASE3; counts_off = 12; in = g_buf0; outp = g_roots; break;
    }

    int k_ex  = blockIdx.y;
    int count = g_counts[counts_off + k_ex];
    int m0    = blockIdx.x * 64;
    if (m0 >= count) return;

    int* s_node = (int*)(smem + SN_O);
    if (tid < 64)
        s_node[tid] = (m0 + tid < count) ? g_lists[list_base + k_ex * stride + m0 + tid] : -1;
    __syncthreads();

    const float* b1p = b1 + k_ex * TWO_E;
    const float* b2p = b2 + k_ex * E;
    const u32* w1h = g_w1h + k_ex * 256 * 128;
    const u32* w1l = g_w1l + k_ex * 256 * 128;
    const u32* w2h = g_w2h + k_ex * 128 * 128;
    const u32* w2l = g_w2l + k_ex * 128 * 128;

    // ---- stage X -> As hi/lo (64 rows x 256 cols bf16, stride 528) --------
    {
        int m = tid >> 2, q = tid & 3;
        int node = s_node[m];
        for (int i = 0; i < 32; i++) {
            int kp = q * 32 + i;
            int col = 2 * kp;
            float x0 = 0.f, x1 = 0.f;
            if (node >= 0) {
                if (lvl == 0) {
                    int l = (col < E) ? leaf_idx[2 * node] : leaf_idx[2 * node + 1];
                    float2 v = *(const float2*)(ent_emb + (size_t)l * E + (col & (E - 1)));
                    x0 = v.x; x1 = v.y;
                } else {
                    float2 v = *(const float2*)(in + (size_t)node * TWO_E + col);
                    x0 = v.x; x1 = v.y;
                }
            }
            u32 hp, lp; split2(x0, x1, hp, lp);
            *(u32*)(smem + AS_HI + m * 528 + kp * 4) = hp;
            *(u32*)(smem + AS_LO + m * 528 + kp * 4) = lp;
        }
    }

    // ---- stage B1 chunk 0 (stride 80B, 16B-aligned rows) -------------------
    {
        const u32* sh = w1h + tid * 128;
        const u32* sl = w1l + tid * 128;
        #pragma unroll
        for (int j = 0; j < 16; j++) {
            *(u32*)(smem + BB_HI + tid * 80 + j * 4) = __ldg(sh + j);
            *(u32*)(smem + BB_LO + tid * 80 + j * 4) = __ldg(sl + j);
        }
    }
    __syncthreads();

    int arow  = (lane & 7) + ((lane >> 3) & 1) * 8;
    int acolo = (lane >> 4) * 8;
    int bn  = (lane & 7) + (lane >> 4) * 8;
    int bko = ((lane >> 3) & 1) * 8;

    // =================== GEMM1: C[64,256] = X @ W1 =========================
    float acc[2][8][4];
    #pragma unroll
    for (int mf = 0; mf < 2; mf++)
        #pragma unroll
        for (int nf = 0; nf < 8; nf++)
            #pragma unroll
            for (int j = 0; j < 4; j++) acc[mf][nf][j] = 0.f;

    for (int cc = 0; cc < 8; cc++) {
        #pragma unroll
        for (int ks = 0; ks < 2; ks++) {
            u32 ah[2][4], al[2][4];
            int acol = cc * 32 + ks * 16 + acolo;
            #pragma unroll
            for (int mf = 0; mf < 2; mf++) {
                int row = wm * 32 + mf * 16 + arow;
                u32 ad = sb + AS_HI + row * 528 + acol * 2;
                LDMX4(ah[mf], ad);
                LDMX4(al[mf], ad + 33792);
            }
            #pragma unroll
            for (int p = 0; p < 4; p++) {
                int n = wn * 64 + p * 16 + bn;
                u32 bd = sb + BB_HI + n * 80 + (ks * 16 + bko) * 2;
                u32 t[4];
                LDMX4(t, bd);                          // hi
                MMA_BF16(acc[0][2*p],   ah[0], t[0], t[1]);
                MMA_BF16(acc[1][2*p],   ah[1], t[0], t[1]);
                MMA_BF16(acc[0][2*p+1], ah[0], t[2], t[3]);
                MMA_BF16(acc[1][2*p+1], ah[1], t[2], t[3]);
                MMA_BF16(acc[0][2*p],   al[0], t[0], t[1]);
                MMA_BF16(acc[1][2*p],   al[1], t[0], t[1]);
                MMA_BF16(acc[0][2*p+1], al[0], t[2], t[3]);
                MMA_BF16(acc[1][2*p+1], al[1], t[2], t[3]);
                LDMX4(t, bd + 20480);                  // lo
                MMA_BF16(acc[0][2*p],   ah[0], t[0], t[1]);
                MMA_BF16(acc[1][2*p],   ah[1], t[0], t[1]);
                MMA_BF16(acc[0][2*p+1], ah[0], t[2], t[3]);
                MMA_BF16(acc[1][2*p+1], ah[1], t[2], t[3]);
            }
        }
        __syncthreads();
        if (cc < 7) {
            const u32* sh = w1h + tid * 128 + (cc + 1) * 16;
            const u32* sl = w1l + tid * 128 + (cc + 1) * 16;
            #pragma unroll
            for (int j = 0; j < 16; j++) {
                *(u32*)(smem + BB_HI + tid * 80 + j * 4) = __ldg(sh + j);
                *(u32*)(smem + BB_LO + tid * 80 + j * 4) = __ldg(sl + j);
            }
            __syncthreads();
        }
    }

    // ---- epilogue1: bias+relu, split, H overwrites As ----------------------
    {
        int g4 = lane >> 2, c4 = lane & 3;
        #pragma unroll
        for (int mf = 0; mf < 2; mf++)
            #pragma unroll
            for (int nf = 0; nf < 8; nf++) {
                int col = wn * 64 + nf * 8 + 2 * c4;
                float2 bv = *(const float2*)(b1p + col);
                int row = wm * 32 + mf * 16 + g4;
                float v0 = fmaxf(acc[mf][nf][0] + bv.x, 0.f);
                float v1 = fmaxf(acc[mf][nf][1] + bv.y, 0.f);
                u32 hp, lp; split2(v0, v1, hp, lp);
                *(u32*)(smem + AS_HI + row * 528 + col * 2) = hp;
                *(u32*)(smem + AS_LO + row * 528 + col * 2) = lp;
                float v2 = fmaxf(acc[mf][nf][2] + bv.x, 0.f);
                float v3 = fmaxf(acc[mf][nf][3] + bv.y, 0.f);
                split2(v2, v3, hp, lp);
                *(u32*)(smem + AS_HI + (row + 8) * 528 + col * 2) = hp;
                *(u32*)(smem + AS_LO + (row + 8) * 528 + col * 2) = lp;
            }
    }
    // ---- stage B2 chunk 0 --------------------------------------------------
    {
        int n = tid >> 1, j0 = (tid & 1) * 8;
        const u32* sh = w2h + n * 128 + j0;
        const u32* sl = w2l + n * 128 + j0;
        #pragma unroll
        for (int j = 0; j < 8; j++) {
            *(u32*)(smem + BB_HI + n * 80 + (j0 + j) * 4) = __ldg(sh + j);
            *(u32*)(smem + BB_LO + n * 80 + (j0 + j) * 4) = __ldg(sl + j);
        }
    }
    __syncthreads();

    // =================== GEMM2: O[64,128] = H @ W2 =========================
    float a2[2][4][4];
    #pragma unroll
    for (int mf = 0; mf < 2; mf++)
        #pragma unroll
        for (int nf = 0; nf < 4; nf++)
            #pragma unroll
            for (int j = 0; j < 4; j++) a2[mf][nf][j] = 0.f;

    for (int cc = 0; cc < 8; cc++) {
        #pragma unroll
        for (int ks = 0; ks < 2; ks++) {
            u32 ah[2][4], al[2][4];
            int acol = cc * 32 + ks * 16 + acolo;
            #pragma unroll
            for (int mf = 0; mf < 2; mf++) {
                int row = wm * 32 + mf * 16 + arow;
                u32 ad = sb + AS_HI + row * 528 + acol * 2;
                LDMX4(ah[mf], ad);
                LDMX4(al[mf], ad + 33792);
            }
            #pragma unroll
            for (int p = 0; p < 2; p++) {
                int n = wn * 32 + p * 16 + bn;
                u32 bd = sb + BB_HI + n * 80 + (ks * 16 + bko) * 2;
                u32 t[4];
                LDMX4(t, bd);                          // hi
                MMA_BF16(a2[0][2*p],   ah[0], t[0], t[1]);
                MMA_BF16(a2[1][2*p],   ah[1], t[0], t[1]);
                MMA_BF16(a2[0][2*p+1], ah[0], t[2], t[3]);
                MMA_BF16(a2[1][2*p+1], ah[1], t[2], t[3]);
                MMA_BF16(a2[0][2*p],   al[0], t[0], t[1]);
                MMA_BF16(a2[1][2*p],   al[1], t[0], t[1]);
                MMA_BF16(a2[0][2*p+1], al[0], t[2], t[3]);
                MMA_BF16(a2[1][2*p+1], al[1], t[2], t[3]);
                LDMX4(t, bd + 20480);                  // lo
                MMA_BF16(a2[0][2*p],   ah[0], t[0], t[1]);
                MMA_BF16(a2[1][2*p],   ah[1], t[0], t[1]);
                MMA_BF16(a2[0][2*p+1], ah[0], t[2], t[3]);
                MMA_BF16(a2[1][2*p+1], ah[1], t[2], t[3]);
            }
        }
        __syncthreads();
        if (cc < 7) {
            int n = tid >> 1, j0 = (tid & 1) * 8;
            const u32* sh = w2h + n * 128 + (cc + 1) * 16 + j0;
            const u32* sl = w2l + n * 128 + (cc + 1) * 16 + j0;
            #pragma unroll
            for (int j = 0; j < 8; j++) {
                *(u32*)(smem + BB_HI + n * 80 + (j0 + j) * 4) = __ldg(sh + j);
                *(u32*)(smem + BB_LO + n * 80 + (j0 + j) * 4) = __ldg(sl + j);
            }
            __syncthreads();
        }
    }

    // ---- epilogue2: bias + store to gmem -----------------------------------
    {
        int g4 = lane >> 2, c4 = lane & 3;
        #pragma unroll
        for (int mf = 0; mf < 2; mf++)
            #pragma unroll
            for (int nf = 0; nf < 4; nf++) {
                int col = wn * 32 + nf * 8 + 2 * c4;
                float2 bv = *(const float2*)(b2p + col);
                int row = wm * 32 + mf * 16 + g4;
                int nd = s_node[row];
                if (nd >= 0) {
                    float2 o;
                    o.x = a2[mf][nf][0] + bv.x;
                    o.y = a2[mf][nf][1] + bv.y;
                    *(float2*)(outp + (size_t)nd * E + col) = o;
                }
                int nd2 = s_node[row + 8];
                if (nd2 >= 0) {
                    float2 o;
                    o.x = a2[mf][nf][2] + bv.x;
                    o.y = a2[mf][nf][3] + bv.y;
                    *(float2*)(outp + (size_t)nd2 * E + col) = o;
                }
            }
    }
}

// ---------------------------------------------------------------------------
// lf expert MLP: 256 -> relu(512) -> 128 (scalar packed-f32x2; ~3% of FLOPs)
// ---------------------------------------------------------------------------
__global__ void __launch_bounds__(256, 1)
lf_gemm_kernel(const float* __restrict__ W1, const float* __restrict__ b1,
               const float* __restrict__ W2, const float* __restrict__ b2) {
    extern __shared__ char smem[];
    float* Xt = (float*)(smem + LF_XT_OFF);
    float* Ht = (float*)(smem + LF_HT_OFF);
    float* Ws = (float*)(smem + LF_WS_OFF);
    int* s_node = (int*)(smem + LF_SN_OFF);

    int k_ex  = blockIdx.y;
    int count = g_counts[16 + k_ex];
    int m0    = blockIdx.x * TMLF;
    if (m0 >= count) return;
    int mrows = min(TMLF, count - m0);
    int tid   = threadIdx.x;

    if (tid < TMLF)
        s_node[tid] = (tid < mrows) ? g_lists[LBASE4 + k_ex * LFN + m0 + tid] : -1;
    __syncthreads();

    {
        int wid = tid >> 5, lane = tid & 31;
        #pragma unroll
        for (int i = 0; i < 4; i++) {
            int m = wid * 4 + i;
            int node = s_node[m];
            const float* src = 0;
            if (node >= 0) {
                int b = node / 9, g = node % 9;
                src = g_roots + ((size_t)b * Tt + 16 + 2 * g) * E;
            }
            #pragma unroll
            for (int j = 0; j < 8; j++) {
                int k = lane + 32 * j;
                Xt[k * XSTR + m] = src ? src[k] : 0.f;
            }
        }
    }

    int rg = tid & 7,  cg = tid >> 3;
    int r0 = rg * 4,   c0 = cg * 8;
    const float* W1k = W1 + (size_t)k_ex * TWO_E * 512;

    for (int pass = 0; pass < 2; pass++) {
        ull acc[4][4];
        #pragma unroll
        for (int i = 0; i < 4; i++)
            #pragma unroll
            for (int j = 0; j < 4; j++) acc[i][j] = 0ull;

        float4 pre[8];
        {
            #pragma unroll
            for (int i = 0; i < 8; i++) {
                int f = tid + i * 256, r = f >> 6, c4 = f & 63;
                pre[i] = __ldg((const float4*)W1k + (size_t)r * 128 + pass * 64 + c4);
            }
        }
        for (int cb = 0; cb < 8; cb++) {
            float4* Wsv = (float4*)Ws;
            #pragma unroll
            for (int i = 0; i < 8; i++) Wsv[tid + i * 256] = pre[i];
            __syncthreads();
            if (cb < 7) {
                #pragma unroll
                for (int i = 0; i < 8; i++) {
                    int f = tid + i * 256, r = f >> 6, c4 = f & 63;
                    pre[i] = __ldg((const float4*)W1k
                                   + (size_t)((cb + 1) * 32 + r) * 128 + pass * 64 + c4);
                }
            }
            #pragma unroll
            for (int kk = 0; kk < 32; kk++) {
                float4 x = *(const float4*)&Xt[(cb * 32 + kk) * XSTR + r0];
                ulonglong2 wa = *(const ulonglong2*)&Ws[kk * 256 + c0];
                ulonglong2 wb = *(const ulonglong2*)&Ws[kk * 256 + c0 + 4];
                ull xd[4] = {pack_dup(x.x), pack_dup(x.y), pack_dup(x.z), pack_dup(x.w)};
                #pragma unroll
                for (int i = 0; i < 4; i++) {
                    fma2(acc[i][0], xd[i], wa.x);
                    fma2(acc[i][1], xd[i], wa.y);
                    fma2(acc[i][2], xd[i], wb.x);
                    fma2(acc[i][3], xd[i], wb.y);
                }
            }
            __syncthreads();
        }
        int cabs = pass * 256 + c0;
        float4 bva = __ldg((const float4*)(b1 + k_ex * 512 + cabs));
        float4 bvb = __ldg((const float4*)(b1 + k_ex * 512 + cabs + 4));
        float bv[8] = {bva.x, bva.y, bva.z, bva.w, bvb.x, bvb.y, bvb.z, bvb.w};
        float a[4][8];
        #pragma unroll
        for (int i = 0; i < 4; i++)
            #pragma unroll
            for (int jp = 0; jp < 4; jp++) {
                float2 p = unpack2(acc[i][jp]);
                a[i][2 * jp]     = p.x;
                a[i][2 * jp + 1] = p.y;
            }
        #pragma unroll
        for (int j = 0; j < 8; j++) {
            float4 h;
            h.x = fmaxf(a[0][j] + bv[j], 0.f);
            h.y = fmaxf(a[1][j] + bv[j], 0.f);
            h.z = fmaxf(a[2][j] + bv[j], 0.f);
            h.w = fmaxf(a[3][j] + bv[j], 0.f);
            *(float4*)&Ht[(cabs + j) * XSTR + r0] = h;
        }
    }
    __syncthreads();

    int c2 = (tid >> 3) * 4;
    ull a2[4][2];
    #pragma unroll
    for (int i = 0; i < 4; i++) { a2[i][0] = 0ull; a2[i][1] = 0ull; }

    const float* W2k = W2 + (size_t)k_ex * 512 * E;
    float4 p2[4];
    {
        const float4* src = (const float4*)W2k;
        #pragma unroll
        for (int i = 0; i < 4; i++) p2[i] = __ldg(&src[tid + i * 256]);
    }
    for (int cb = 0; cb < 16; cb++) {
        float4* Wsv = (float4*)Ws;
        #pragma unroll
        for (int i = 0; i < 4; i++) Wsv[tid + i * 256] = p2[i];
        __syncthreads();
        if (cb < 15) {
            const float4* src = (const float4*)(W2k + (size_t)(cb + 1) * 32 * E);
            #pragma unroll
            for (int i = 0; i < 4; i++) p2[i] = __ldg(&src[tid + i * 256]);
        }
        #pragma unroll
        for (int kk = 0; kk < 32; kk++) {
            float4 h = *(const float4*)&Ht[(cb * 32 + kk) * XSTR + r0];
            ulonglong2 w = *(const ulonglong2*)&Ws[kk * E + c2];
            ull hd[4] = {pack_dup(h.x), pack_dup(h.y), pack_dup(h.z), pack_dup(h.w)};
            #pragma unroll
            for (int i = 0; i < 4; i++) {
                fma2(a2[i][0], hd[i], w.x);
                fma2(a2[i][1], hd[i], w.y);
            }
        }
        __syncthreads();
    }
    {
        float4 bv = __ldg((const float4*)(b2 + k_ex * E + c2));
        #pragma unroll
        for (int i = 0; i < 4; i++) {
            int node = s_node[r0 + i];
            if (node >= 0) {
                float2 pa = unpack2(a2[i][0]);
                float2 pb = unpack2(a2[i][1]);
                float4 o;
                o.x = pa.x + bv.x; o.y = pa.y + bv.y;
                o.z = pb.x + bv.z; o.w = pb.y + bv.w;
                *(float4*)(g_stmt + (size_t)node * E + c2) = o;
            }
        }
    }
}

// ---------------------------------------------------------------------------
// Attention tail (unchanged)
// ---------------------------------------------------------------------------
__global__ void attn_kernel(const int* __restrict__ th_idx,
                            const float* __restrict__ th_emb,
                            const float* __restrict__ he_W, const float* __restrict__ he_b,
                            const float* __restrict__ hg_W, const float* __restrict__ hg_b,
                            const float* __restrict__ ht_W, const float* __restrict__ ht_b,
                            float* __restrict__ out) {
    __shared__ float obj[E];
    __shared__ float q[E];
    __shared__ float keys[16][E + 1];
    __shared__ float a[16];
    int b = blockIdx.x, tid = threadIdx.x;

    float o = g_stmt[((size_t)b * 9 + 8) * E + tid];
    obj[tid] = o;
    out[(size_t)b * 512 + tid] = o;
    __syncthreads();

    for (int t3 = 0; t3 < 3; t3++) {
        int n; const float *W, *bb;
        if (t3 == 0) {
            n = 8; W = hg_W; bb = hg_b;
            for (int i = 0; i < 8; i++)
                keys[i][tid] = g_stmt[((size_t)b * 9 + i) * E + tid];
        } else if (t3 == 1) {
            n = 16; W = he_W; bb = he_b;
            for (int i = 0; i < 16; i++)
                keys[i][tid] = g_roots[((size_t)b * Tt + i) * E + tid];
        } else {
            n = 8; W = ht_W; bb = ht_b;
            for (int i = 0; i < 8; i++)
                keys[i][tid] = th_emb[(size_t)th_idx[b * 8 + i] * E + tid];
        }
        float qv = bb[tid];
        for (int k = 0; k < E; k++) qv = fmaf(obj[k], W[k * E + tid], qv);
        q[tid] = qv;
        __syncthreads();
        if (tid < n) {
            float s = 0.f;
            for (int d = 0; d < E; d++) s = fmaf(keys[tid][d], q[d], s);
            a[tid] = s;
        }
        __syncthreads();
        if (tid == 0) {
            float mx = -1e30f;
            for (int i = 0; i < n; i++) mx = fmaxf(mx, a[i]);
            float sum = 0.f;
            for (int i = 0; i < n; i++) { float e = expf(a[i] - mx); a[i] = e; sum += e; }
            float inv = 1.f / sum;
            for (int i = 0; i < n; i++) a[i] *= inv;
        }
        __syncthreads();
        float c = 0.f;
        for (int i = 0; i < n; i++) c = fmaf(a[i], keys[i][tid], c);
        int off = (t3 == 0) ? 128 : (t3 == 1) ? 256 : 384;
        out[(size_t)b * 512 + off + tid] = c;
        __syncthreads();
    }
}

// ---------------------------------------------------------------------------
extern "C" void kernel_launch(void* const* d_in, const int* in_sizes, int n_in,
                              void* d_out, int out_size) {
    const int*   leaf_idx = (const int*)d_in[0];
    const int*   nf_ids   = (const int*)d_in[1];
    const int*   lf_ids   = (const int*)d_in[2];
    const int*   th_idx   = (const int*)d_in[3];
    const float* ent_emb  = (const float*)d_in[4];
    const float* th_emb   = (const float*)d_in[5];
    const float* nf_W1 = (const float*)d_in[6];
    const float* nf_b1 = (const float*)d_in[7];
    const float* nf_W2 = (const float*)d_in[8];
    const float* nf_b2 = (const float*)d_in[9];
    const float* lf_W1 = (const float*)d_in[10];
    const float* lf_b1 = (const float*)d_in[11];
    const float* lf_W2 = (const float*)d_in[12];
    const float* lf_b2 = (const float*)d_in[13];
    const float* he_W = (const float*)d_in[14];
    const float* he_b = (const float*)d_in[15];
    const float* hg_W = (const float*)d_in[16];
    const float* hg_b = (const float*)d_in[17];
    const float* ht_W = (const float*)d_in[18];
    const float* ht_b = (const float*)d_in[19];
    float* out = (float*)d_out;

    cudaFuncSetAttribute(nf_mma_kernel, cudaFuncAttributeMaxDynamicSharedMemorySize, NF_SMEM);
    cudaFuncSetAttribute(lf_gemm_kernel, cudaFuncAttributeMaxDynamicSharedMemorySize, LF_SMEM);

    zero_counts_kernel<<<1, 32>>>();
    compact_kernel<<<(L0N + L1N + L2N + L3N + LFN) / 256, 256>>>(nf_ids, lf_ids);
    prep_w_kernel<<<(4 * 256 * 128 + 4 * 128 * 128) / 256, 256>>>(nf_W1, nf_W2);

    nf_mma_kernel<<<dim3(L0N / 64, 4), 256, NF_SMEM>>>(0, leaf_idx, ent_emb, nf_b1, nf_b2);
    nf_mma_kernel<<<dim3(L1N / 64, 4), 256, NF_SMEM>>>(1, leaf_idx, ent_emb, nf_b1, nf_b2);
    nf_mma_kernel<<<dim3(L2N / 64, 4), 256, NF_SMEM>>>(2, leaf_idx, ent_emb, nf_b1, nf_b2);
    nf_mma_kernel<<<dim3(L3N / 64, 4), 256, NF_SMEM>>>(3, leaf_idx, ent_emb, nf_b1, nf_b2);

    lf_gemm_kernel<<<dim3(LFN / TMLF, 3), 256, LF_SMEM>>>(lf_W1, lf_b1, lf_W2, lf_b2);

    attn_kernel<<<Bn, E>>>(th_idx, th_emb, he_W, he_b, hg_W, hg_b, ht_W, ht_b, out);
}

// round 15
// speedup vs baseline: 2.6925x; 2.6925x over previous
#include <cuda_runtime.h>
#include <cuda_bf16.h>

typedef unsigned long long ull;
typedef unsigned int u32;

// ---------------------------------------------------------------------------
// Problem constants
// ---------------------------------------------------------------------------
#define Bn      1024
#define Tt      34
#define E       128
#define TWO_E   256
#define L0N     (Bn*Tt*8)    // 278528
#define L1N     (Bn*Tt*4)    // 139264
#define L2N     (Bn*Tt*2)    // 69632
#define L3N     (Bn*Tt)      // 34816
#define LFN     (Bn*9)       // 9216
#define LBASE0  0
#define LBASE1  (LBASE0 + 4*L0N)
#define LBASE2  (LBASE1 + 4*L1N)
#define LBASE3  (LBASE2 + 4*L2N)
#define LBASE4  (LBASE3 + 4*L3N)
#define LTOTAL  (LBASE4 + 3*LFN)

// ---- nf HMMA kernel geometry ----------------------------------------------
// M=64 rows/block, 8 warps (wm = wid>>2, wn = wid&3), 2 blocks/SM.
// A (X then H overlay) bf16 hi/lo, row stride 528B (16B-aligned).
// B: one 32-k buffer = two 16-k slots (at ks*32B in each 80B row), used as a
// 2-deep cp.async pipeline from pre-layouted global weights.
#define AS_HI   0
#define AS_LO   33792                  // 64*528
#define BB_HI   67584
#define BB_LO   (BB_HI + 20480)        // 88064   (256*80)
#define SN_O    (BB_LO + 20480)        // 108544
#define NF_SMEM (SN_O + 256)           // 108800  (x2 = 217600 <= 228KB/SM)

// ---- lf scalar kernel geometry (unchanged, ~3% of FLOPs) -------------------
#define TMLF    32
#define XSTR    36
#define LF_XT_OFF   0
#define LF_HT_OFF   36864
#define LF_WS_OFF   (36864 + 73728)
#define LF_SN_OFF   (LF_WS_OFF + 32768)
#define LF_SMEM     (LF_SN_OFF + 128)

// ---------------------------------------------------------------------------
// PTX helpers
// ---------------------------------------------------------------------------
__device__ __forceinline__ u32 smem_u32(const void* p) {
    u32 a;
    asm("{ .reg .u64 t; cvta.to.shared.u64 t, %1; cvt.u32.u64 %0, t; }"
        : "=r"(a) : "l"(p));
    return a;
}

#define LDMX4(r, addr) \
    asm volatile("ldmatrix.sync.aligned.m8n8.x4.shared.b16 {%0,%1,%2,%3}, [%4];" \
        : "=r"((r)[0]), "=r"((r)[1]), "=r"((r)[2]), "=r"((r)[3]) : "r"(addr))

#define MMA_BF16(d, a, b0, b1) \
    asm volatile("mma.sync.aligned.m16n8k16.row.col.f32.bf16.bf16.f32 " \
        "{%0,%1,%2,%3}, {%4,%5,%6,%7}, {%8,%9}, {%0,%1,%2,%3};" \
        : "+f"((d)[0]), "+f"((d)[1]), "+f"((d)[2]), "+f"((d)[3]) \
        : "r"((a)[0]), "r"((a)[1]), "r"((a)[2]), "r"((a)[3]), \
          "r"(b0), "r"(b1))

#define CP16(dst, src) \
    asm volatile("cp.async.cg.shared.global [%0], [%1], 16;" \
        :: "r"(dst), "l"(src) : "memory")
#define CP_COMMIT() asm volatile("cp.async.commit_group;" ::: "memory")
#define CP_WAIT1()  asm volatile("cp.async.wait_group 1;" ::: "memory")
#define CP_WAIT0()  asm volatile("cp.async.wait_group 0;" ::: "memory")

// split fp32 pair -> packed bf16 hi pair + lo pair (x ~= hi + lo to ~2^-17)
__device__ __forceinline__ void split2(float v0, float v1, u32& hp, u32& lp) {
    __nv_bfloat16 h0 = __float2bfloat16_rn(v0);
    __nv_bfloat16 h1 = __float2bfloat16_rn(v1);
    float r0 = v0 - __bfloat162float(h0);
    float r1 = v1 - __bfloat162float(h1);
    __nv_bfloat16 l0 = __float2bfloat16_rn(r0);
    __nv_bfloat16 l1 = __float2bfloat16_rn(r1);
    hp = (u32)__bfloat16_as_ushort(h0) | ((u32)__bfloat16_as_ushort(h1) << 16);
    lp = (u32)__bfloat16_as_ushort(l0) | ((u32)__bfloat16_as_ushort(l1) << 16);
}

// ---------------------------------------------------------------------------
// Packed fp32x2 helpers (lf scalar kernel)
// ---------------------------------------------------------------------------
__device__ __forceinline__ void fma2(ull& d, ull a, ull b) {
    asm("fma.rn.f32x2 %0, %1, %2, %0;" : "+l"(d) : "l"(a), "l"(b));
}
__device__ __forceinline__ ull pack_dup(float w) {
    ull r; unsigned wi = __float_as_uint(w);
    asm("mov.b64 %0, {%1, %2};" : "=l"(r) : "r"(wi), "r"(wi));
    return r;
}
__device__ __forceinline__ float2 unpack2(ull v) {
    unsigned lo, hi;
    asm("mov.b64 {%0, %1}, %2;" : "=r"(lo), "=r"(hi) : "l"(v));
    float2 f; f.x = __uint_as_float(lo); f.y = __uint_as_float(hi);
    return f;
}

// ---------------------------------------------------------------------------
// Scratch (device globals; no allocation allowed)
// ---------------------------------------------------------------------------
__device__ float g_buf0[(size_t)L0N * E];
__device__ float g_buf1[(size_t)L1N * E];
__device__ float g_roots[(size_t)L3N * E];
__device__ float g_stmt[(size_t)LFN * E];
__device__ int   g_counts[20];
__device__ int   g_lists[LTOTAL];
// staged weights in cp.async order:
//   g_w1s[((e*16+h)*4+q)*256+tid], q: 0=hi p0, 1=hi p1, 2=lo p0, 3=lo p1
//   g_w2s[((e*16+h)*2+q)*256+tid], q: 0=hi, 1=lo
__device__ uint4 g_w1s[4 * 16 * 4 * 256];   // 1 MB
__device__ uint4 g_w2s[4 * 16 * 2 * 256];   // 0.5 MB

__global__ void zero_counts_kernel() {
    if (threadIdx.x < 20) g_counts[threadIdx.x] = 0;
}

// ---------------------------------------------------------------------------
// Weight pre-layout: fp32 -> packed bf16 hi/lo uint4 in staging order
// ---------------------------------------------------------------------------
__global__ void prep_w_kernel(const float* __restrict__ W1,
                              const float* __restrict__ W2) {
    int t = blockIdx.x * 256 + threadIdx.x;
    if (t < 4 * 16 * 4 * 256) {
        int e = t >> 14, h = (t >> 10) & 15, q = (t >> 8) & 3, n = t & 255;
        const float* W = W1 + (size_t)e * TWO_E * TWO_E;
        u32 v[4];
        #pragma unroll
        for (int j = 0; j < 4; j++) {
            int kp = h * 8 + (q & 1) * 4 + j;
            float w0 = W[(size_t)(2 * kp) * TWO_E + n];
            float w1 = W[(size_t)(2 * kp + 1) * TWO_E + n];
            u32 hp, lp; split2(w0, w1, hp, lp);
            v[j] = (q < 2) ? hp : lp;
        }
        g_w1s[t] = make_uint4(v[0], v[1], v[2], v[3]);
    } else {
        int t2 = t - 4 * 16 * 4 * 256;
        int e = t2 >> 13, h = (t2 >> 9) & 15, q = (t2 >> 8) & 1, tid = t2 & 255;
        int n = tid >> 1, part = tid & 1;
        const float* W = W2 + (size_t)e * TWO_E * E;
        u32 v[4];
        #pragma unroll
        for (int j = 0; j < 4; j++) {
            int kp = h * 8 + part * 4 + j;
            float w0 = W[(size_t)(2 * kp) * E + n];
            float w1 = W[(size_t)(2 * kp + 1) * E + n];
            u32 hp, lp; split2(w0, w1, hp, lp);
            v[j] = (q == 0) ? hp : lp;
        }
        g_w2s[t2] = make_uint4(v[0], v[1], v[2], v[3]);
    }
}

// ---------------------------------------------------------------------------
// Expert compaction (warp-aggregated atomics)
// ---------------------------------------------------------------------------
__global__ void compact_kernel(const int* __restrict__ nf_ids,
                               const int* __restrict__ lf_ids) {
    int gid = blockIdx.x * 256 + threadIdx.x;
    int slot, store_base, nid;
    if (gid < L0N) {
        nid = gid;
        int bt = nid >> 3, j = nid & 7;
        int id = nf_ids[bt * 15 + j];
        slot = id;               store_base = LBASE0 + id * L0N;
    } else if (gid < L0N + L1N) {
        nid = gid - L0N;
        int bt = nid >> 2, j = nid & 3;
        int id = nf_ids[bt * 15 + 8 + j];
        slot = 4 + id;           store_base = LBASE1 + id * L1N;
    } else if (gid < L0N + L1N + L2N) {
        nid = gid - (L0N + L1N);
        int bt = nid >> 1, j = nid & 1;
        int id = nf_ids[bt * 15 + 12 + j];
        slot = 8 + id;           store_base = LBASE2 + id * L2N;
    } else if (gid < L0N + L1N + L2N + L3N) {
        nid = gid - (L0N + L1N + L2N);
        int id = nf_ids[nid * 15 + 14];
        slot = 12 + id;          store_base = LBASE3 + id * L3N;
    } else {
        nid = gid - (L0N + L1N + L2N + L3N);
        int id = lf_ids[nid];
        slot = 16 + id;          store_base = LBASE4 + id * LFN;
    }
    unsigned mm = __match_any_sync(0xFFFFFFFFu, slot);
    int lane   = threadIdx.x & 31;
    int leader = __ffs(mm) - 1;
    int rank   = __popc(mm & ((1u << lane) - 1));
    int base   = 0;
    if (lane == leader) base = atomicAdd(&g_counts[slot], __popc(mm));
    base = __shfl_sync(0xFFFFFFFFu, base, leader);
    g_lists[store_base + base + rank] = nid;
}

// ---------------------------------------------------------------------------
// nf expert MLP on HMMA (split-bf16, fp32 accum), 2 blocks/SM,
// cp.async 2-deep half-chunk pipeline for B.
// ---------------------------------------------------------------------------
__global__ void __launch_bounds__(256, 2)
nf_mma_kernel(int lvl,
              const int* __restrict__ leaf_idx,
              const float* __restrict__ ent_emb,
              const float* __restrict__ b1, const float* __restrict__ b2) {
    extern __shared__ char smem[];
    u32 sb = smem_u32(smem);
    int tid = threadIdx.x, wid = tid >> 5, lane = tid & 31;
    int wm = wid >> 2, wn = wid & 3;

    int stride, list_base, counts_off;
    const float* in; float* outp;
    switch (lvl) {
        case 0:  stride = L0N; list_base = LBASE0; counts_off = 0;  in = 0;      outp = g_buf0;  break;
        case 1:  stride = L1N; list_base = LBASE1; counts_off = 4;  in = g_buf0; outp = g_buf1;  break;
        case 2:  stride = L2N; list_base = LBASE2; counts_off = 8;  in = g_buf1; outp = g_buf0;  break;
        default: stride = L3N; list_base = LBASE3; counts_off = 12; in = g_buf0; outp = g_roots; break;
    }

    int k_ex  = blockIdx.y;
    int count = g_counts[counts_off + k_ex];
    int m0    = blockIdx.x * 64;
    if (m0 >= count) return;

    int* s_node = (int*)(smem + SN_O);
    if (tid < 64)
        s_node[tid] = (m0 + tid < count) ? g_lists[list_base + k_ex * stride + m0 + tid] : -1;
    __syncthreads();

    const float* b1p = b1 + k_ex * TWO_E;
    const float* b2p = b2 + k_ex * E;
    const uint4* w1s = g_w1s + (size_t)k_ex * 16 * 4 * 256;
    const uint4* w2s = g_w2s + (size_t)k_ex * 16 * 2 * 256;

    // ---- stage X -> As hi/lo (64 rows x 256 cols bf16, stride 528) --------
    {
        int m = tid >> 2, q = tid & 3;
        int node = s_node[m];
        for (int i = 0; i < 32; i++) {
            int kp = q * 32 + i;
            int col = 2 * kp;
            float x0 = 0.f, x1 = 0.f;
            if (node >= 0) {
                if (lvl == 0) {
                    int l = (col < E) ? leaf_idx[2 * node] : leaf_idx[2 * node + 1];
                    float2 v = *(const float2*)(ent_emb + (size_t)l * E + (col & (E - 1)));
                    x0 = v.x; x1 = v.y;
                } else {
                    float2 v = *(const float2*)(in + (size_t)node * TWO_E + col);
                    x0 = v.x; x1 = v.y;
                }
            }
            u32 hp, lp; split2(x0, x1, hp, lp);
            *(u32*)(smem + AS_HI + m * 528 + kp * 4) = hp;
            *(u32*)(smem + AS_LO + m * 528 + kp * 4) = lp;
        }
    }

    int arow  = (lane & 7) + ((lane >> 3) & 1) * 8;
    int acolo = (lane >> 4) * 8;
    int bn  = (lane & 7) + (lane >> 4) * 8;
    int bko2 = ((lane >> 3) & 1) * 16;     // B k byte offset within slot

    // ---- B1 stage helper: half h -> slot (h&1) -----------------------------
    #define STAGE_W1(h) do { \
        u32 so = (u32)(((h) & 1) * 32); \
        const uint4* s = w1s + (h) * 4 * 256; \
        CP16(sb + BB_HI + tid * 80 + so,      (const void*)(s + 0 * 256 + tid)); \
        CP16(sb + BB_HI + tid * 80 + so + 16, (const void*)(s + 1 * 256 + tid)); \
        CP16(sb + BB_LO + tid * 80 + so,      (const void*)(s + 2 * 256 + tid)); \
        CP16(sb + BB_LO + tid * 80 + so + 16, (const void*)(s + 3 * 256 + tid)); \
        CP_COMMIT(); \
    } while (0)

    #define STAGE_W2(h) do { \
        int nrow = tid >> 1, part = tid & 1; \
        u32 dd = (u32)(nrow * 80 + ((h) & 1) * 32 + part * 16); \
        const uint4* s = w2s + (h) * 2 * 256; \
        CP16(sb + BB_HI + dd, (const void*)(s + 0 * 256 + tid)); \
        CP16(sb + BB_LO + dd, (const void*)(s + 1 * 256 + tid)); \
        CP_COMMIT(); \
    } while (0)

    // =================== GEMM1: C[64,256] = X @ W1 =========================
    float acc[2][8][4];
    #pragma unroll
    for (int mf = 0; mf < 2; mf++)
        #pragma unroll
        for (int nf = 0; nf < 8; nf++)
            #pragma unroll
            for (int j = 0; j < 4; j++) acc[mf][nf][j] = 0.f;

    STAGE_W1(0);
    STAGE_W1(1);
    for (int h = 0; h < 16; h++) {
        if (h == 15) { CP_WAIT0(); } else { CP_WAIT1(); }
        __syncthreads();
        {
            u32 ah[2][4], al[2][4];
            int acol = h * 16 + acolo;
            #pragma unroll
            for (int mf = 0; mf < 2; mf++) {
                int row = wm * 32 + mf * 16 + arow;
                u32 ad = sb + AS_HI + row * 528 + acol * 2;
                LDMX4(ah[mf], ad);
                LDMX4(al[mf], ad + 33792);
            }
            #pragma unroll
            for (int p = 0; p < 4; p++) {
                int n = wn * 64 + p * 16 + bn;
                u32 bd = sb + BB_HI + n * 80 + (h & 1) * 32 + bko2;
                u32 t[4];
                LDMX4(t, bd);                          // hi
                MMA_BF16(acc[0][2*p],   ah[0], t[0], t[1]);
                MMA_BF16(acc[1][2*p],   ah[1], t[0], t[1]);
                MMA_BF16(acc[0][2*p+1], ah[0], t[2], t[3]);
                MMA_BF16(acc[1][2*p+1], ah[1], t[2], t[3]);
                MMA_BF16(acc[0][2*p],   al[0], t[0], t[1]);
                MMA_BF16(acc[1][2*p],   al[1], t[0], t[1]);
                MMA_BF16(acc[0][2*p+1], al[0], t[2], t[3]);
                MMA_BF16(acc[1][2*p+1], al[1], t[2], t[3]);
                LDMX4(t, bd + 20480);                  // lo
                MMA_BF16(acc[0][2*p],   ah[0], t[0], t[1]);
                MMA_BF16(acc[1][2*p],   ah[1], t[0], t[1]);
                MMA_BF16(acc[0][2*p+1], ah[0], t[2], t[3]);
                MMA_BF16(acc[1][2*p+1], ah[1], t[2], t[3]);
            }
        }
        __syncthreads();
        if (h < 14) STAGE_W1(h + 2);
    }

    // ---- epilogue1: bias+relu, split, H overwrites As ----------------------
    {
        int g4 = lane >> 2, c4 = lane & 3;
        #pragma unroll
        for (int mf = 0; mf < 2; mf++)
            #pragma unroll
            for (int nf = 0; nf < 8; nf++) {
                int col = wn * 64 + nf * 8 + 2 * c4;
                float2 bv = *(const float2*)(b1p + col);
                int row = wm * 32 + mf * 16 + g4;
                float v0 = fmaxf(acc[mf][nf][0] + bv.x, 0.f);
                float v1 = fmaxf(acc[mf][nf][1] + bv.y, 0.f);
                u32 hp, lp; split2(v0, v1, hp, lp);
                *(u32*)(smem + AS_HI + row * 528 + col * 2) = hp;
                *(u32*)(smem + AS_LO + row * 528 + col * 2) = lp;
                float v2 = fmaxf(acc[mf][nf][2] + bv.x, 0.f);
                float v3 = fmaxf(acc[mf][nf][3] + bv.y, 0.f);
                split2(v2, v3, hp, lp);
                *(u32*)(smem + AS_HI + (row + 8) * 528 + col * 2) = hp;
                *(u32*)(smem + AS_LO + (row + 8) * 528 + col * 2) = lp;
            }
    }

    // =================== GEMM2: O[64,128] = H @ W2 =========================
    float a2[2][4][4];
    #pragma unroll
    for (int mf = 0; mf < 2; mf++)
        #pragma unroll
        for (int nf = 0; nf < 4; nf++)
            #pragma unroll
            for (int j = 0; j < 4; j++) a2[mf][nf][j] = 0.f;

    STAGE_W2(0);
    STAGE_W2(1);
    for (int h = 0; h < 16; h++) {
        if (h == 15) { CP_WAIT0(); } else { CP_WAIT1(); }
        __syncthreads();
        {
            u32 ah[2][4], al[2][4];
            int acol = h * 16 + acolo;
            #pragma unroll
            for (int mf = 0; mf < 2; mf++) {
                int row = wm * 32 + mf * 16 + arow;
                u32 ad = sb + AS_HI + row * 528 + acol * 2;
                LDMX4(ah[mf], ad);
                LDMX4(al[mf], ad + 33792);
            }
            #pragma unroll
            for (int p = 0; p < 2; p++) {
                int n = wn * 32 + p * 16 + bn;
                u32 bd = sb + BB_HI + n * 80 + (h & 1) * 32 + bko2;
                u32 t[4];
                LDMX4(t, bd);                          // hi
                MMA_BF16(a2[0][2*p],   ah[0], t[0], t[1]);
                MMA_BF16(a2[1][2*p],   ah[1], t[0], t[1]);
                MMA_BF16(a2[0][2*p+1], ah[0], t[2], t[3]);
                MMA_BF16(a2[1][2*p+1], ah[1], t[2], t[3]);
                MMA_BF16(a2[0][2*p],   al[0], t[0], t[1]);
                MMA_BF16(a2[1][2*p],   al[1], t[0], t[1]);
                MMA_BF16(a2[0][2*p+1], al[0], t[2], t[3]);
                MMA_BF16(a2[1][2*p+1], al[1], t[2], t[3]);
                LDMX4(t, bd + 20480);                  // lo
                MMA_BF16(a2[0][2*p],   ah[0], t[0], t[1]);
                MMA_BF16(a2[1][2*p],   ah[1], t[0], t[1]);
                MMA_BF16(a2[0][2*p+1], ah[0], t[2], t[3]);
                MMA_BF16(a2[1][2*p+1], ah[1], t[2], t[3]);
            }
        }
        __syncthreads();
        if (h < 14) STAGE_W2(h + 2);
    }

    // ---- epilogue2: bias + store to gmem -----------------------------------
    {
        int g4 = lane >> 2, c4 = lane & 3;
        #pragma unroll
        for (int mf = 0; mf < 2; mf++)
            #pragma unroll
            for (int nf = 0; nf < 4; nf++) {
                int col = wn * 32 + nf * 8 + 2 * c4;
                float2 bv = *(const float2*)(b2p + col);
                int row = wm * 32 + mf * 16 + g4;
                int nd = s_node[row];
                if (nd >= 0) {
                    float2 o;
                    o.x = a2[mf][nf][0] + bv.x;
                    o.y = a2[mf][nf][1] + bv.y;
                    *(float2*)(outp + (size_t)nd * E + col) = o;
                }
                int nd2 = s_node[row + 8];
                if (nd2 >= 0) {
                    float2 o;
                    o.x = a2[mf][nf][2] + bv.x;
                    o.y = a2[mf][nf][3] + bv.y;
                    *(float2*)(outp + (size_t)nd2 * E + col) = o;
                }
            }
    }
    #undef STAGE_W1
    #undef STAGE_W2
}

// ---------------------------------------------------------------------------
// lf expert MLP: 256 -> relu(512) -> 128 (scalar packed-f32x2; ~3% of FLOPs)
// ---------------------------------------------------------------------------
__global__ void __launch_bounds__(256, 1)
lf_gemm_kernel(const float* __restrict__ W1, const float* __restrict__ b1,
               const float* __restrict__ W2, const float* __restrict__ b2) {
    extern __shared__ char smem[];
    float* Xt = (float*)(smem + LF_XT_OFF);
    float* Ht = (float*)(smem + LF_HT_OFF);
    float* Ws = (float*)(smem + LF_WS_OFF);
    int* s_node = (int*)(smem + LF_SN_OFF);

    int k_ex  = blockIdx.y;
    int count = g_counts[16 + k_ex];
    int m0    = blockIdx.x * TMLF;
    if (m0 >= count) return;
    int mrows = min(TMLF, count - m0);
    int tid   = threadIdx.x;

    if (tid < TMLF)
        s_node[tid] = (tid < mrows) ? g_lists[LBASE4 + k_ex * LFN + m0 + tid] : -1;
    __syncthreads();

    {
        int wid = tid >> 5, lane = tid & 31;
        #pragma unroll
        for (int i = 0; i < 4; i++) {
            int m = wid * 4 + i;
            int node = s_node[m];
            const float* src = 0;
            if (node >= 0) {
                int b = node / 9, g = node % 9;
                src = g_roots + ((size_t)b * Tt + 16 + 2 * g) * E;
            }
            #pragma unroll
            for (int j = 0; j < 8; j++) {
                int k = lane + 32 * j;
                Xt[k * XSTR + m] = src ? src[k] : 0.f;
            }
        }
    }

    int rg = tid & 7,  cg = tid >> 3;
    int r0 = rg * 4,   c0 = cg * 8;
    const float* W1k = W1 + (size_t)k_ex * TWO_E * 512;

    for (int pass = 0; pass < 2; pass++) {
        ull acc[4][4];
        #pragma unroll
        for (int i = 0; i < 4; i++)
            #pragma unroll
            for (int j = 0; j < 4; j++) acc[i][j] = 0ull;

        float4 pre[8];
        {
            #pragma unroll
            for (int i = 0; i < 8; i++) {
                int f = tid + i * 256, r = f >> 6, c4 = f & 63;
                pre[i] = __ldg((const float4*)W1k + (size_t)r * 128 + pass * 64 + c4);
            }
        }
        for (int cb = 0; cb < 8; cb++) {
            float4* Wsv = (float4*)Ws;
            #pragma unroll
            for (int i = 0; i < 8; i++) Wsv[tid + i * 256] = pre[i];
            __syncthreads();
            if (cb < 7) {
                #pragma unroll
                for (int i = 0; i < 8; i++) {
                    int f = tid + i * 256, r = f >> 6, c4 = f & 63;
                    pre[i] = __ldg((const float4*)W1k
                                   + (size_t)((cb + 1) * 32 + r) * 128 + pass * 64 + c4);
                }
            }
            #pragma unroll
            for (int kk = 0; kk < 32; kk++) {
                float4 x = *(const float4*)&Xt[(cb * 32 + kk) * XSTR + r0];
                ulonglong2 wa = *(const ulonglong2*)&Ws[kk * 256 + c0];
                ulonglong2 wb = *(const ulonglong2*)&Ws[kk * 256 + c0 + 4];
                ull xd[4] = {pack_dup(x.x), pack_dup(x.y), pack_dup(x.z), pack_dup(x.w)};
                #pragma unroll
                for (int i = 0; i < 4; i++) {
                    fma2(acc[i][0], xd[i], wa.x);
                    fma2(acc[i][1], xd[i], wa.y);
                    fma2(acc[i][2], xd[i], wb.x);
                    fma2(acc[i][3], xd[i], wb.y);
                }
            }
            __syncthreads();
        }
        int cabs = pass * 256 + c0;
        float4 bva = __ldg((const float4*)(b1 + k_ex * 512 + cabs));
        float4 bvb = __ldg((const float4*)(b1 + k_ex * 512 + cabs + 4));
        float bv[8] = {bva.x, bva.y, bva.z, bva.w, bvb.x, bvb.y, bvb.z, bvb.w};
        float a[4][8];
        #pragma unroll
        for (int i = 0; i < 4; i++)
            #pragma unroll
            for (int jp = 0; jp < 4; jp++) {
                float2 p = unpack2(acc[i][jp]);
                a[i][2 * jp]     = p.x;
                a[i][2 * jp + 1] = p.y;
            }
        #pragma unroll
        for (int j = 0; j < 8; j++) {
            float4 h;
            h.x = fmaxf(a[0][j] + bv[j], 0.f);
            h.y = fmaxf(a[1][j] + bv[j], 0.f);
            h.z = fmaxf(a[2][j] + bv[j], 0.f);
            h.w = fmaxf(a[3][j] + bv[j], 0.f);
            *(float4*)&Ht[(cabs + j) * XSTR + r0] = h;
        }
    }
    __syncthreads();

    int c2 = (tid >> 3) * 4;
    ull a2[4][2];
    #pragma unroll
    for (int i = 0; i < 4; i++) { a2[i][0] = 0ull; a2[i][1] = 0ull; }

    const float* W2k = W2 + (size_t)k_ex * 512 * E;
    float4 p2[4];
    {
        const float4* src = (const float4*)W2k;
        #pragma unroll
        for (int i = 0; i < 4; i++) p2[i] = __ldg(&src[tid + i * 256]);
    }
    for (int cb = 0; cb < 16; cb++) {
        float4* Wsv = (float4*)Ws;
        #pragma unroll
        for (int i = 0; i < 4; i++) Wsv[tid + i * 256] = p2[i];
        __syncthreads();
        if (cb < 15) {
            const float4* src = (const float4*)(W2k + (size_t)(cb + 1) * 32 * E);
            #pragma unroll
            for (int i = 0; i < 4; i++) p2[i] = __ldg(&src[tid + i * 256]);
        }
        #pragma unroll
        for (int kk = 0; kk < 32; kk++) {
            float4 h = *(const float4*)&Ht[(cb * 32 + kk) * XSTR + r0];
            ulonglong2 w = *(const ulonglong2*)&Ws[kk * E + c2];
            ull hd[4] = {pack_dup(h.x), pack_dup(h.y), pack_dup(h.z), pack_dup(h.w)};
            #pragma unroll
            for (int i = 0; i < 4; i++) {
                fma2(a2[i][0], hd[i], w.x);
                fma2(a2[i][1], hd[i], w.y);
            }
        }
        __syncthreads();
    }
    {
        float4 bv = __ldg((const float4*)(b2 + k_ex * E + c2));
        #pragma unroll
        for (int i = 0; i < 4; i++) {
            int node = s_node[r0 + i];
            if (node >= 0) {
                float2 pa = unpack2(a2[i][0]);
                float2 pb = unpack2(a2[i][1]);
                float4 o;
                o.x = pa.x + bv.x; o.y = pa.y + bv.y;
                o.z = pb.x + bv.z; o.w = pb.y + bv.w;
                *(float4*)(g_stmt + (size_t)node * E + c2) = o;
            }
        }
    }
}

// ---------------------------------------------------------------------------
// Attention tail (unchanged)
// ---------------------------------------------------------------------------
__global__ void attn_kernel(const int* __restrict__ th_idx,
                            const float* __restrict__ th_emb,
                            const float* __restrict__ he_W, const float* __restrict__ he_b,
                            const float* __restrict__ hg_W, const float* __restrict__ hg_b,
                            const float* __restrict__ ht_W, const float* __restrict__ ht_b,
                            float* __restrict__ out) {
    __shared__ float obj[E];
    __shared__ float q[E];
    __shared__ float keys[16][E + 1];
    __shared__ float a[16];
    int b = blockIdx.x, tid = threadIdx.x;

    float o = g_stmt[((size_t)b * 9 + 8) * E + tid];
    obj[tid] = o;
    out[(size_t)b * 512 + tid] = o;
    __syncthreads();

    for (int t3 = 0; t3 < 3; t3++) {
        int n; const float *W, *bb;
        if (t3 == 0) {
            n = 8; W = hg_W; bb = hg_b;
            for (int i = 0; i < 8; i++)
                keys[i][tid] = g_stmt[((size_t)b * 9 + i) * E + tid];
        } else if (t3 == 1) {
            n = 16; W = he_W; bb = he_b;
            for (int i = 0; i < 16; i++)
                keys[i][tid] = g_roots[((size_t)b * Tt + i) * E + tid];
        } else {
            n = 8; W = ht_W; bb = ht_b;
            for (int i = 0; i < 8; i++)
                keys[i][tid] = th_emb[(size_t)th_idx[b * 8 + i] * E + tid];
        }
        float qv = bb[tid];
        for (int k = 0; k < E; k++) qv = fmaf(obj[k], W[k * E + tid], qv);
        q[tid] = qv;
        __syncthreads();
        if (tid < n) {
            float s = 0.f;
            for (int d = 0; d < E; d++) s = fmaf(keys[tid][d], q[d], s);
            a[tid] = s;
        }
        __syncthreads();
        if (tid == 0) {
            float mx = -1e30f;
            for (int i = 0; i < n; i++) mx = fmaxf(mx, a[i]);
            float sum = 0.f;
            for (int i = 0; i < n; i++) { float e = expf(a[i] - mx); a[i] = e; sum += e; }
            float inv = 1.f / sum;
            for (int i = 0; i < n; i++) a[i] *= inv;
        }
        __syncthreads();
        float c = 0.f;
        for (int i = 0; i < n; i++) c = fmaf(a[i], keys[i][tid], c);
        int off = (t3 == 0) ? 128 : (t3 == 1) ? 256 : 384;
        out[(size_t)b * 512 + off + tid] = c;
        __syncthreads();
    }
}

// ---------------------------------------------------------------------------
extern "C" void kernel_launch(void* const* d_in, const int* in_sizes, int n_in,
                              void* d_out, int out_size) {
    const int*   leaf_idx = (const int*)d_in[0];
    const int*   nf_ids   = (const int*)d_in[1];
    const int*   lf_ids   = (const int*)d_in[2];
    const int*   th_idx   = (const int*)d_in[3];
    const float* ent_emb  = (const float*)d_in[4];
    const float* th_emb   = (const float*)d_in[5];
    const float* nf_W1 = (const float*)d_in[6];
    const float* nf_b1 = (const float*)d_in[7];
    const float* nf_W2 = (const float*)d_in[8];
    const float* nf_b2 = (const float*)d_in[9];
    const float* lf_W1 = (const float*)d_in[10];
    const float* lf_b1 = (const float*)d_in[11];
    const float* lf_W2 = (const float*)d_in[12];
    const float* lf_b2 = (const float*)d_in[13];
    const float* he_W = (const float*)d_in[14];
    const float* he_b = (const float*)d_in[15];
    const float* hg_W = (const float*)d_in[16];
    const float* hg_b = (const float*)d_in[17];
    const float* ht_W = (const float*)d_in[18];
    const float* ht_b = (const float*)d_in[19];
    float* out = (float*)d_out;

    cudaFuncSetAttribute(nf_mma_kernel, cudaFuncAttributeMaxDynamicSharedMemorySize, NF_SMEM);
    cudaFuncSetAttribute(lf_gemm_kernel, cudaFuncAttributeMaxDynamicSharedMemorySize, LF_SMEM);

    zero_counts_kernel<<<1, 32>>>();
    compact_kernel<<<(L0N + L1N + L2N + L3N + LFN) / 256, 256>>>(nf_ids, lf_ids);
    prep_w_kernel<<<(4 * 16 * 4 * 256 + 4 * 16 * 2 * 256) / 256, 256>>>(nf_W1, nf_W2);

    nf_mma_kernel<<<dim3(L0N / 64, 4), 256, NF_SMEM>>>(0, leaf_idx, ent_emb, nf_b1, nf_b2);
    nf_mma_kernel<<<dim3(L1N / 64, 4), 256, NF_SMEM>>>(1, leaf_idx, ent_emb, nf_b1, nf_b2);
    nf_mma_kernel<<<dim3(L2N / 64, 4), 256, NF_SMEM>>>(2, leaf_idx, ent_emb, nf_b1, nf_b2);
    nf_mma_kernel<<<dim3(L3N / 64, 4), 256, NF_SMEM>>>(3, leaf_idx, ent_emb, nf_b1, nf_b2);

    lf_gemm_kernel<<<dim3(LFN / TMLF, 3), 256, LF_SMEM>>>(lf_W1, lf_b1, lf_W2, lf_b2);

    attn_kernel<<<Bn, E>>>(th_idx, th_emb, he_W, he_b, hg_W, hg_b, ht_W, ht_b, out);
}

// round 16
// speedup vs baseline: 3.1518x; 1.1706x over previous
#include <cuda_runtime.h>
#include <cuda_bf16.h>

typedef unsigned long long ull;
typedef unsigned int u32;

// ---------------------------------------------------------------------------
// Problem constants
// ---------------------------------------------------------------------------
#define Bn      1024
#define Tt      34
#define E       128
#define TWO_E   256
#define L0N     (Bn*Tt*8)    // 278528
#define L1N     (Bn*Tt*4)    // 139264
#define L2N     (Bn*Tt*2)    // 69632
#define L3N     (Bn*Tt)      // 34816
#define LFN     (Bn*9)       // 9216
#define LBASE0  0
#define LBASE1  (LBASE0 + 4*L0N)
#define LBASE2  (LBASE1 + 4*L1N)
#define LBASE3  (LBASE2 + 4*L2N)
#define LBASE4  (LBASE3 + 4*L3N)
#define LTOTAL  (LBASE4 + 3*LFN)

// ---- nf HMMA kernel geometry ----------------------------------------------
#define AS_HI   0
#define AS_LO   33792                  // 64*528
#define BB_HI   67584
#define BB_LO   (BB_HI + 20480)        // 88064   (256*80)
#define SN_O    (BB_LO + 20480)        // 108544
#define NF_SMEM (SN_O + 256)           // 108800  (x2 = 217600 <= 228KB/SM)

// ---- lf scalar kernel geometry --------------------------------------------
#define TMLF    32
#define XSTR    36
#define LF_XT_OFF   0
#define LF_HT_OFF   36864
#define LF_WS_OFF   (36864 + 73728)
#define LF_SN_OFF   (LF_WS_OFF + 32768)
#define LF_SMEM     (LF_SN_OFF + 128)

// ---------------------------------------------------------------------------
// PTX helpers
// ---------------------------------------------------------------------------
__device__ __forceinline__ u32 smem_u32(const void* p) {
    u32 a;
    asm("{ .reg .u64 t; cvta.to.shared.u64 t, %1; cvt.u32.u64 %0, t; }"
        : "=r"(a) : "l"(p));
    return a;
}

#define LDMX4(r, addr) \
    asm volatile("ldmatrix.sync.aligned.m8n8.x4.shared.b16 {%0,%1,%2,%3}, [%4];" \
        : "=r"((r)[0]), "=r"((r)[1]), "=r"((r)[2]), "=r"((r)[3]) : "r"(addr))

#define MMA_BF16(d, a, b0, b1) \
    asm volatile("mma.sync.aligned.m16n8k16.row.col.f32.bf16.bf16.f32 " \
        "{%0,%1,%2,%3}, {%4,%5,%6,%7}, {%8,%9}, {%0,%1,%2,%3};" \
        : "+f"((d)[0]), "+f"((d)[1]), "+f"((d)[2]), "+f"((d)[3]) \
        : "r"((a)[0]), "r"((a)[1]), "r"((a)[2]), "r"((a)[3]), \
          "r"(b0), "r"(b1))

#define CP16(dst, src) \
    asm volatile("cp.async.cg.shared.global [%0], [%1], 16;" \
        :: "r"(dst), "l"(src) : "memory")
#define CP_COMMIT() asm volatile("cp.async.commit_group;" ::: "memory")
#define CP_WAIT1()  asm volatile("cp.async.wait_group 1;" ::: "memory")
#define CP_WAIT0()  asm volatile("cp.async.wait_group 0;" ::: "memory")

// split fp32 pair -> packed bf16 hi pair + lo pair (x ~= hi + lo to ~2^-17)
__device__ __forceinline__ void split2(float v0, float v1, u32& hp, u32& lp) {
    __nv_bfloat16 h0 = __float2bfloat16_rn(v0);
    __nv_bfloat16 h1 = __float2bfloat16_rn(v1);
    float r0 = v0 - __bfloat162float(h0);
    float r1 = v1 - __bfloat162float(h1);
    __nv_bfloat16 l0 = __float2bfloat16_rn(r0);
    __nv_bfloat16 l1 = __float2bfloat16_rn(r1);
    hp = (u32)__bfloat16_as_ushort(h0) | ((u32)__bfloat16_as_ushort(h1) << 16);
    lp = (u32)__bfloat16_as_ushort(l0) | ((u32)__bfloat16_as_ushort(l1) << 16);
}

// ---------------------------------------------------------------------------
// Packed fp32x2 helpers (lf scalar kernel)
// ---------------------------------------------------------------------------
__device__ __forceinline__ void fma2(ull& d, ull a, ull b) {
    asm("fma.rn.f32x2 %0, %1, %2, %0;" : "+l"(d) : "l"(a), "l"(b));
}
__device__ __forceinline__ ull pack_dup(float w) {
    ull r; unsigned wi = __float_as_uint(w);
    asm("mov.b64 %0, {%1, %2};" : "=l"(r) : "r"(wi), "r"(wi));
    return r;
}
__device__ __forceinline__ float2 unpack2(ull v) {
    unsigned lo, hi;
    asm("mov.b64 {%0, %1}, %2;" : "=r"(lo), "=r"(hi) : "l"(v));
    float2 f; f.x = __uint_as_float(lo); f.y = __uint_as_float(hi);
    return f;
}

// ---------------------------------------------------------------------------
// Scratch (device globals; no allocation allowed)
// ---------------------------------------------------------------------------
__device__ float g_buf0[(size_t)L0N * E];
__device__ float g_buf1[(size_t)L1N * E];
__device__ float g_roots[(size_t)L3N * E];
__device__ float g_stmt[(size_t)LFN * E];
__device__ int   g_counts[20];
__device__ int   g_lists[LTOTAL];
// staged weights in cp.async order
__device__ uint4 g_w1s[4 * 16 * 4 * 256];   // 1 MB
__device__ uint4 g_w2s[4 * 16 * 2 * 256];   // 0.5 MB

__global__ void zero_counts_kernel() {
    if (threadIdx.x < 20) g_counts[threadIdx.x] = 0;
}

// ---------------------------------------------------------------------------
// Weight pre-layout: fp32 -> packed bf16 hi/lo uint4 in staging order
// ---------------------------------------------------------------------------
__global__ void prep_w_kernel(const float* __restrict__ W1,
                              const float* __restrict__ W2) {
    int t = blockIdx.x * 256 + threadIdx.x;
    if (t < 4 * 16 * 4 * 256) {
        int e = t >> 14, h = (t >> 10) & 15, q = (t >> 8) & 3, n = t & 255;
        const float* W = W1 + (size_t)e * TWO_E * TWO_E;
        u32 v[4];
        #pragma unroll
        for (int j = 0; j < 4; j++) {
            int kp = h * 8 + (q & 1) * 4 + j;
            float w0 = W[(size_t)(2 * kp) * TWO_E + n];
            float w1 = W[(size_t)(2 * kp + 1) * TWO_E + n];
            u32 hp, lp; split2(w0, w1, hp, lp);
            v[j] = (q < 2) ? hp : lp;
        }
        g_w1s[t] = make_uint4(v[0], v[1], v[2], v[3]);
    } else {
        int t2 = t - 4 * 16 * 4 * 256;
        int e = t2 >> 13, h = (t2 >> 9) & 15, q = (t2 >> 8) & 1, tid = t2 & 255;
        int n = tid >> 1, part = tid & 1;
        const float* W = W2 + (size_t)e * TWO_E * E;
        u32 v[4];
        #pragma unroll
        for (int j = 0; j < 4; j++) {
            int kp = h * 8 + part * 4 + j;
            float w0 = W[(size_t)(2 * kp) * E + n];
            float w1 = W[(size_t)(2 * kp + 1) * E + n];
            u32 hp, lp; split2(w0, w1, hp, lp);
            v[j] = (q == 0) ? hp : lp;
        }
        g_w2s[t2] = make_uint4(v[0], v[1], v[2], v[3]);
    }
}

// ---------------------------------------------------------------------------
// Expert compaction (warp-aggregated atomics)
// ---------------------------------------------------------------------------
__global__ void compact_kernel(const int* __restrict__ nf_ids,
                               const int* __restrict__ lf_ids) {
    int gid = blockIdx.x * 256 + threadIdx.x;
    int slot, store_base, nid;
    if (gid < L0N) {
        nid = gid;
        int bt = nid >> 3, j = nid & 7;
        int id = nf_ids[bt * 15 + j];
        slot = id;               store_base = LBASE0 + id * L0N;
    } else if (gid < L0N + L1N) {
        nid = gid - L0N;
        int bt = nid >> 2, j = nid & 3;
        int id = nf_ids[bt * 15 + 8 + j];
        slot = 4 + id;           store_base = LBASE1 + id * L1N;
    } else if (gid < L0N + L1N + L2N) {
        nid = gid - (L0N + L1N);
        int bt = nid >> 1, j = nid & 1;
        int id = nf_ids[bt * 15 + 12 + j];
        slot = 8 + id;           store_base = LBASE2 + id * L2N;
    } else if (gid < L0N + L1N + L2N + L3N) {
        nid = gid - (L0N + L1N + L2N);
        int id = nf_ids[nid * 15 + 14];
        slot = 12 + id;          store_base = LBASE3 + id * L3N;
    } else {
        nid = gid - (L0N + L1N + L2N + L3N);
        int id = lf_ids[nid];
        slot = 16 + id;          store_base = LBASE4 + id * LFN;
    }
    unsigned mm = __match_any_sync(0xFFFFFFFFu, slot);
    int lane   = threadIdx.x & 31;
    int leader = __ffs(mm) - 1;
    int rank   = __popc(mm & ((1u << lane) - 1));
    int base   = 0;
    if (lane == leader) base = atomicAdd(&g_counts[slot], __popc(mm));
    base = __shfl_sync(0xFFFFFFFFu, base, leader);
    g_lists[store_base + base + rank] = nid;
}

// ---------------------------------------------------------------------------
// nf expert MLP on HMMA (split-bf16, fp32 accum), 2 blocks/SM,
// cp.async 2-deep half-chunk pipeline for B. Compacted flat grid.
// ---------------------------------------------------------------------------
__global__ void __launch_bounds__(256, 2)
nf_mma_kernel(int lvl,
              const int* __restrict__ leaf_idx,
              const float* __restrict__ ent_emb,
              const float* __restrict__ b1, const float* __restrict__ b2) {
    extern __shared__ char smem[];
    u32 sb = smem_u32(smem);
    int tid = threadIdx.x, wid = tid >> 5, lane = tid & 31;
    int wm = wid >> 2, wn = wid & 3;

    int stride, list_base, counts_off;
    const float* in; float* outp;
    switch (lvl) {
        case 0:  stride = L0N; list_base = LBASE0; counts_off = 0;  in = 0;      outp = g_buf0;  break;
        case 1:  stride = L1N; list_base = LBASE1; counts_off = 4;  in = g_buf0; outp = g_buf1;  break;
        case 2:  stride = L2N; list_base = LBASE2; counts_off = 8;  in = g_buf1; outp = g_buf0;  break;
        default: stride = L3N; list_base = LBASE3; counts_off = 12; in = g_buf0; outp = g_roots; break;
    }

    // ---- flat-grid expert derivation (ceil-prefix over 4 counts) -----------
    int c0 = g_counts[counts_off + 0];
    int c1 = g_counts[counts_off + 1];
    int c2c = g_counts[counts_off + 2];
    int c3 = g_counts[counts_off + 3];
    int nb0 = (c0 + 63) >> 6, nb1 = (c1 + 63) >> 6, nb2 = (c2c + 63) >> 6;
    int nb3 = (c3 + 63) >> 6;
    int bid = blockIdx.x;
    int k_ex, m0, count;
    if (bid < nb0)                        { k_ex = 0; m0 = bid * 64;                     count = c0;  }
    else if (bid < nb0 + nb1)             { k_ex = 1; m0 = (bid - nb0) * 64;             count = c1;  }
    else if (bid < nb0 + nb1 + nb2)       { k_ex = 2; m0 = (bid - nb0 - nb1) * 64;       count = c2c; }
    else if (bid < nb0 + nb1 + nb2 + nb3) { k_ex = 3; m0 = (bid - nb0 - nb1 - nb2) * 64; count = c3;  }
    else return;

    int* s_node = (int*)(smem + SN_O);
    if (tid < 64)
        s_node[tid] = (m0 + tid < count) ? g_lists[list_base + k_ex * stride + m0 + tid] : -1;
    __syncthreads();

    const float* b1p = b1 + k_ex * TWO_E;
    const float* b2p = b2 + k_ex * E;
    const uint4* w1s = g_w1s + (size_t)k_ex * 16 * 4 * 256;
    const uint4* w2s = g_w2s + (size_t)k_ex * 16 * 2 * 256;

    // ---- B1 stage helper: half h -> slot (h&1) -----------------------------
    #define STAGE_W1(h) do { \
        u32 so = (u32)(((h) & 1) * 32); \
        const uint4* s = w1s + (h) * 4 * 256; \
        CP16(sb + BB_HI + tid * 80 + so,      (const void*)(s + 0 * 256 + tid)); \
        CP16(sb + BB_HI + tid * 80 + so + 16, (const void*)(s + 1 * 256 + tid)); \
        CP16(sb + BB_LO + tid * 80 + so,      (const void*)(s + 2 * 256 + tid)); \
        CP16(sb + BB_LO + tid * 80 + so + 16, (const void*)(s + 3 * 256 + tid)); \
        CP_COMMIT(); \
    } while (0)

    #define STAGE_W2(h) do { \
        int nrow = tid >> 1, part = tid & 1; \
        u32 dd = (u32)(nrow * 80 + ((h) & 1) * 32 + part * 16); \
        const uint4* s = w2s + (h) * 2 * 256; \
        CP16(sb + BB_HI + dd, (const void*)(s + 0 * 256 + tid)); \
        CP16(sb + BB_LO + dd, (const void*)(s + 1 * 256 + tid)); \
        CP_COMMIT(); \
    } while (0)

    // W1 chunks 0/1 land while we stage X (long LDG/split section below).
    STAGE_W1(0);
    STAGE_W1(1);

    // ---- stage X -> As hi/lo: coalesced float4 loads, uint2 stores ---------
    // thread: m = tid>>2, q = tid&3; u = i*4+q covers 64 float4 per row.
    {
        int m = tid >> 2, q = tid & 3;
        int node = s_node[m];
        int l0 = 0, l1 = 0;
        if (lvl == 0 && node >= 0) { l0 = leaf_idx[2 * node]; l1 = leaf_idx[2 * node + 1]; }
        const float* srcA = (lvl != 0 && node >= 0) ? (in + (size_t)node * TWO_E) : 0;
        #pragma unroll
        for (int i = 0; i < 16; i++) {
            int u = i * 4 + q;             // float4 index 0..63
            int col = u * 4;               // 0,4,...,252
            float4 v = make_float4(0.f, 0.f, 0.f, 0.f);
            if (node >= 0) {
                if (lvl == 0) {
                    int l = (col < E) ? l0 : l1;
                    v = *(const float4*)(ent_emb + (size_t)l * E + (col & (E - 1)));
                } else {
                    v = *(const float4*)(srcA + col);
                }
            }
            u32 h0, p0, h1, p1;
            split2(v.x, v.y, h0, p0);
            split2(v.z, v.w, h1, p1);
            *(uint2*)(smem + AS_HI + m * 528 + u * 8) = make_uint2(h0, h1);
            *(uint2*)(smem + AS_LO + m * 528 + u * 8) = make_uint2(p0, p1);
        }
    }

    __syncthreads();

    int arow  = (lane & 7) + ((lane >> 3) & 1) * 8;
    int acolo = (lane >> 4) * 8;
    int bn  = (lane & 7) + (lane >> 4) * 8;
    int bko2 = ((lane >> 3) & 1) * 16;     // B k byte offset within slot

    // =================== GEMM1: C[64,256] = X @ W1 =========================
    float acc[2][8][4];
    #pragma unroll
    for (int mf = 0; mf < 2; mf++)
        #pragma unroll
        for (int nf = 0; nf < 8; nf++)
            #pragma unroll
            for (int j = 0; j < 4; j++) acc[mf][nf][j] = 0.f;

    for (int h = 0; h < 16; h++) {
        if (h == 15) { CP_WAIT0(); } else { CP_WAIT1(); }
        __syncthreads();
        {
            u32 ah[2][4], al[2][4];
            int acol = h * 16 + acolo;
            #pragma unroll
            for (int mf = 0; mf < 2; mf++) {
                int row = wm * 32 + mf * 16 + arow;
                u32 ad = sb + AS_HI + row * 528 + acol * 2;
                LDMX4(ah[mf], ad);
                LDMX4(al[mf], ad + 33792);
            }
            #pragma unroll
            for (int p = 0; p < 4; p++) {
                int n = wn * 64 + p * 16 + bn;
                u32 bd = sb + BB_HI + n * 80 + (h & 1) * 32 + bko2;
                u32 t[4];
                LDMX4(t, bd);                          // hi
                MMA_BF16(acc[0][2*p],   ah[0], t[0], t[1]);
                MMA_BF16(acc[1][2*p],   ah[1], t[0], t[1]);
                MMA_BF16(acc[0][2*p+1], ah[0], t[2], t[3]);
                MMA_BF16(acc[1][2*p+1], ah[1], t[2], t[3]);
                MMA_BF16(acc[0][2*p],   al[0], t[0], t[1]);
                MMA_BF16(acc[1][2*p],   al[1], t[0], t[1]);
                MMA_BF16(acc[0][2*p+1], al[0], t[2], t[3]);
                MMA_BF16(acc[1][2*p+1], al[1], t[2], t[3]);
                LDMX4(t, bd + 20480);                  // lo
                MMA_BF16(acc[0][2*p],   ah[0], t[0], t[1]);
                MMA_BF16(acc[1][2*p],   ah[1], t[0], t[1]);
                MMA_BF16(acc[0][2*p+1], ah[0], t[2], t[3]);
                MMA_BF16(acc[1][2*p+1], ah[1], t[2], t[3]);
            }
        }
        __syncthreads();
        if (h < 14) STAGE_W1(h + 2);
    }

    // W2 chunks 0/1 land while epilogue1 computes (B buffer is free here).
    STAGE_W2(0);
    STAGE_W2(1);

    // ---- epilogue1: bias+relu, split, H overwrites As ----------------------
    {
        int g4 = lane >> 2, c4 = lane & 3;
        #pragma unroll
        for (int mf = 0; mf < 2; mf++)
            #pragma unroll
            for (int nf = 0; nf < 8; nf++) {
                int col = wn * 64 + nf * 8 + 2 * c4;
                float2 bv = *(const float2*)(b1p + col);
                int row = wm * 32 + mf * 16 + g4;
                float v0 = fmaxf(acc[mf][nf][0] + bv.x, 0.f);
                float v1 = fmaxf(acc[mf][nf][1] + bv.y, 0.f);
                u32 hp, lp; split2(v0, v1, hp, lp);
                *(u32*)(smem + AS_HI + row * 528 + col * 2) = hp;
                *(u32*)(smem + AS_LO + row * 528 + col * 2) = lp;
                float v2 = fmaxf(acc[mf][nf][2] + bv.x, 0.f);
                float v3 = fmaxf(acc[mf][nf][3] + bv.y, 0.f);
                split2(v2, v3, hp, lp);
                *(u32*)(smem + AS_HI + (row + 8) * 528 + col * 2) = hp;
                *(u32*)(smem + AS_LO + (row + 8) * 528 + col * 2) = lp;
            }
    }

    // =================== GEMM2: O[64,128] = H @ W2 =========================
    float a2[2][4][4];
    #pragma unroll
    for (int mf = 0; mf < 2; mf++)
        #pragma unroll
        for (int nf = 0; nf < 4; nf++)
            #pragma unroll
            for (int j = 0; j < 4; j++) a2[mf][nf][j] = 0.f;

    for (int h = 0; h < 16; h++) {
        if (h == 15) { CP_WAIT0(); } else { CP_WAIT1(); }
        __syncthreads();
        {
            u32 ah[2][4], al[2][4];
            int acol = h * 16 + acolo;
            #pragma unroll
            for (int mf = 0; mf < 2; mf++) {
                int row = wm * 32 + mf * 16 + arow;
                u32 ad = sb + AS_HI + row * 528 + acol * 2;
                LDMX4(ah[mf], ad);
                LDMX4(al[mf], ad + 33792);
            }
            #pragma unroll
            for (int p = 0; p < 2; p++) {
                int n = wn * 32 + p * 16 + bn;
                u32 bd = sb + BB_HI + n * 80 + (h & 1) * 32 + bko2;
                u32 t[4];
                LDMX4(t, bd);                          // hi
                MMA_BF16(a2[0][2*p],   ah[0], t[0], t[1]);
                MMA_BF16(a2[1][2*p],   ah[1], t[0], t[1]);
                MMA_BF16(a2[0][2*p+1], ah[0], t[2], t[3]);
                MMA_BF16(a2[1][2*p+1], ah[1], t[2], t[3]);
                MMA_BF16(a2[0][2*p],   al[0], t[0], t[1]);
                MMA_BF16(a2[1][2*p],   al[1], t[0], t[1]);
                MMA_BF16(a2[0][2*p+1], al[0], t[2], t[3]);
                MMA_BF16(a2[1][2*p+1], al[1], t[2], t[3]);
                LDMX4(t, bd + 20480);                  // lo
                MMA_BF16(a2[0][2*p],   ah[0], t[0], t[1]);
                MMA_BF16(a2[1][2*p],   ah[1], t[0], t[1]);
                MMA_BF16(a2[0][2*p+1], ah[0], t[2], t[3]);
                MMA_BF16(a2[1][2*p+1], ah[1], t[2], t[3]);
            }
        }
        __syncthreads();
        if (h < 14) STAGE_W2(h + 2);
    }

    // ---- epilogue2: bias + store to gmem -----------------------------------
    {
        int g4 = lane >> 2, c4 = lane & 3;
        #pragma unroll
        for (int mf = 0; mf < 2; mf++)
            #pragma unroll
            for (int nf = 0; nf < 4; nf++) {
                int col = wn * 32 + nf * 8 + 2 * c4;
                float2 bv = *(const float2*)(b2p + col);
                int row = wm * 32 + mf * 16 + g4;
                int nd = s_node[row];
                if (nd >= 0) {
                    float2 o;
                    o.x = a2[mf][nf][0] + bv.x;
                    o.y = a2[mf][nf][1] + bv.y;
                    *(float2*)(outp + (size_t)nd * E + col) = o;
                }
                int nd2 = s_node[row + 8];
                if (nd2 >= 0) {
                    float2 o;
                    o.x = a2[mf][nf][2] + bv.x;
                    o.y = a2[mf][nf][3] + bv.y;
                    *(float2*)(outp + (size_t)nd2 * E + col) = o;
                }
            }
    }
    #undef STAGE_W1
    #undef STAGE_W2
}

// ---------------------------------------------------------------------------
// lf expert MLP: 256 -> relu(512) -> 128 (scalar packed-f32x2; ~3% of FLOPs)
// ---------------------------------------------------------------------------
__global__ void __launch_bounds__(256, 1)
lf_gemm_kernel(const float* __restrict__ W1, const float* __restrict__ b1,
               const float* __restrict__ W2, const float* __restrict__ b2) {
    extern __shared__ char smem[];
    float* Xt = (float*)(smem + LF_XT_OFF);
    float* Ht = (float*)(smem + LF_HT_OFF);
    float* Ws = (float*)(smem + LF_WS_OFF);
    int* s_node = (int*)(smem + LF_SN_OFF);

    int k_ex  = blockIdx.y;
    int count = g_counts[16 + k_ex];
    int m0    = blockIdx.x * TMLF;
    if (m0 >= count) return;
    int mrows = min(TMLF, count - m0);
    int tid   = threadIdx.x;

    if (tid < TMLF)
        s_node[tid] = (tid < mrows) ? g_lists[LBASE4 + k_ex * LFN + m0 + tid] : -1;
    __syncthreads();

    {
        int wid = tid >> 5, lane = tid & 31;
        #pragma unroll
        for (int i = 0; i < 4; i++) {
            int m = wid * 4 + i;
            int node = s_node[m];
            const float* src = 0;
            if (node >= 0) {
                int b = node / 9, g = node % 9;
                src = g_roots + ((size_t)b * Tt + 16 + 2 * g) * E;
            }
            #pragma unroll
            for (int j = 0; j < 8; j++) {
                int k = lane + 32 * j;
                Xt[k * XSTR + m] = src ? src[k] : 0.f;
            }
        }
    }

    int rg = tid & 7,  cg = tid >> 3;
    int r0 = rg * 4,   c0 = cg * 8;
    const float* W1k = W1 + (size_t)k_ex * TWO_E * 512;

    for (int pass = 0; pass < 2; pass++) {
        ull acc[4][4];
        #pragma unroll
        for (int i = 0; i < 4; i++)
            #pragma unroll
            for (int j = 0; j < 4; j++) acc[i][j] = 0ull;

        float4 pre[8];
        {
            #pragma unroll
            for (int i = 0; i < 8; i++) {
                int f = tid + i * 256, r = f >> 6, c4 = f & 63;
                pre[i] = __ldg((const float4*)W1k + (size_t)r * 128 + pass * 64 + c4);
            }
        }
        for (int cb = 0; cb < 8; cb++) {
            float4* Wsv = (float4*)Ws;
            #pragma unroll
            for (int i = 0; i < 8; i++) Wsv[tid + i * 256] = pre[i];
            __syncthreads();
            if (cb < 7) {
                #pragma unroll
                for (int i = 0; i < 8; i++) {
                    int f = tid + i * 256, r = f >> 6, c4 = f & 63;
                    pre[i] = __ldg((const float4*)W1k
                                   + (size_t)((cb + 1) * 32 + r) * 128 + pass * 64 + c4);
                }
            }
            #pragma unroll
            for (int kk = 0; kk < 32; kk++) {
                float4 x = *(const float4*)&Xt[(cb * 32 + kk) * XSTR + r0];
                ulonglong2 wa = *(const ulonglong2*)&Ws[kk * 256 + c0];
                ulonglong2 wb = *(const ulonglong2*)&Ws[kk * 256 + c0 + 4];
                ull xd[4] = {pack_dup(x.x), pack_dup(x.y), pack_dup(x.z), pack_dup(x.w)};
                #pragma unroll
                for (int i = 0; i < 4; i++) {
                    fma2(acc[i][0], xd[i], wa.x);
                    fma2(acc[i][1], xd[i], wa.y);
                    fma2(acc[i][2], xd[i], wb.x);
                    fma2(acc[i][3], xd[i], wb.y);
                }
            }
            __syncthreads();
        }
        int cabs = pass * 256 + c0;
        float4 bva = __ldg((const float4*)(b1 + k_ex * 512 + cabs));
        float4 bvb = __ldg((const float4*)(b1 + k_ex * 512 + cabs + 4));
        float bv[8] = {bva.x, bva.y, bva.z, bva.w, bvb.x, bvb.y, bvb.z, bvb.w};
        float a[4][8];
        #pragma unroll
        for (int i = 0; i < 4; i++)
            #pragma unroll
            for (int jp = 0; jp < 4; jp++) {
                float2 p = unpack2(acc[i][jp]);
                a[i][2 * jp]     = p.x;
                a[i][2 * jp + 1] = p.y;
            }
        #pragma unroll
        for (int j = 0; j < 8; j++) {
            float4 h;
            h.x = fmaxf(a[0][j] + bv[j], 0.f);
            h.y = fmaxf(a[1][j] + bv[j], 0.f);
            h.z = fmaxf(a[2][j] + bv[j], 0.f);
            h.w = fmaxf(a[3][j] + bv[j], 0.f);
            *(float4*)&Ht[(cabs + j) * XSTR + r0] = h;
        }
    }
    __syncthreads();

    int c2 = (tid >> 3) * 4;
    ull a2[4][2];
    #pragma unroll
    for (int i = 0; i < 4; i++) { a2[i][0] = 0ull; a2[i][1] = 0ull; }

    const float* W2k = W2 + (size_t)k_ex * 512 * E;
    float4 p2[4];
    {
        const float4* src = (const float4*)W2k;
        #pragma unroll
        for (int i = 0; i < 4; i++) p2[i] = __ldg(&src[tid + i * 256]);
    }
    for (int cb = 0; cb < 16; cb++) {
        float4* Wsv = (float4*)Ws;
        #pragma unroll
        for (int i = 0; i < 4; i++) Wsv[tid + i * 256] = p2[i];
        __syncthreads();
        if (cb < 15) {
            const float4* src = (const float4*)(W2k + (size_t)(cb + 1) * 32 * E);
            #pragma unroll
            for (int i = 0; i < 4; i++) p2[i] = __ldg(&src[tid + i * 256]);
        }
        #pragma unroll
        for (int kk = 0; kk < 32; kk++) {
            float4 h = *(const float4*)&Ht[(cb * 32 + kk) * XSTR + r0];
            ulonglong2 w = *(const ulonglong2*)&Ws[kk * E + c2];
            ull hd[4] = {pack_dup(h.x), pack_dup(h.y), pack_dup(h.z), pack_dup(h.w)};
            #pragma unroll
            for (int i = 0; i < 4; i++) {
                fma2(a2[i][0], hd[i], w.x);
                fma2(a2[i][1], hd[i], w.y);
            }
        }
        __syncthreads();
    }
    {
        float4 bv = __ldg((const float4*)(b2 + k_ex * E + c2));
        #pragma unroll
        for (int i = 0; i < 4; i++) {
            int node = s_node[r0 + i];
            if (node >= 0) {
                float2 pa = unpack2(a2[i][0]);
                float2 pb = unpack2(a2[i][1]);
                float4 o;
                o.x = pa.x + bv.x; o.y = pa.y + bv.y;
                o.z = pb.x + bv.z; o.w = pb.y + bv.w;
                *(float4*)(g_stmt + (size_t)node * E + c2) = o;
            }
        }
    }
}

// ---------------------------------------------------------------------------
// Attention tail (unchanged)
// ---------------------------------------------------------------------------
__global__ void attn_kernel(const int* __restrict__ th_idx,
                            const float* __restrict__ th_emb,
                            const float* __restrict__ he_W, const float* __restrict__ he_b,
                            const float* __restrict__ hg_W, const float* __restrict__ hg_b,
                            const float* __restrict__ ht_W, const float* __restrict__ ht_b,
                            float* __restrict__ out) {
    __shared__ float obj[E];
    __shared__ float q[E];
    __shared__ float keys[16][E + 1];
    __shared__ float a[16];
    int b = blockIdx.x, tid = threadIdx.x;

    float o = g_stmt[((size_t)b * 9 + 8) * E + tid];
    obj[tid] = o;
    out[(size_t)b * 512 + tid] = o;
    __syncthreads();

    for (int t3 = 0; t3 < 3; t3++) {
        int n; const float *W, *bb;
        if (t3 == 0) {
            n = 8; W = hg_W; bb = hg_b;
            for (int i = 0; i < 8; i++)
                keys[i][tid] = g_stmt[((size_t)b * 9 + i) * E + tid];
        } else if (t3 == 1) {
            n = 16; W = he_W; bb = he_b;
            for (int i = 0; i < 16; i++)
                keys[i][tid] = g_roots[((size_t)b * Tt + i) * E + tid];
        } else {
            n = 8; W = ht_W; bb = ht_b;
            for (int i = 0; i < 8; i++)
                keys[i][tid] = th_emb[(size_t)th_idx[b * 8 + i] * E + tid];
        }
        float qv = bb[tid];
        for (int k = 0; k < E; k++) qv = fmaf(obj[k], W[k * E + tid], qv);
        q[tid] = qv;
        __syncthreads();
        if (tid < n) {
            float s = 0.f;
            for (int d = 0; d < E; d++) s = fmaf(keys[tid][d], q[d], s);
            a[tid] = s;
        }
        __syncthreads();
        if (tid == 0) {
            float mx = -1e30f;
            for (int i = 0; i < n; i++) mx = fmaxf(mx, a[i]);
            float sum = 0.f;
            for (int i = 0; i < n; i++) { float e = expf(a[i] - mx); a[i] = e; sum += e; }
            float inv = 1.f / sum;
            for (int i = 0; i < n; i++) a[i] *= inv;
        }
        __syncthreads();
        float c = 0.f;
        for (int i = 0; i < n; i++) c = fmaf(a[i], keys[i][tid], c);
        int off = (t3 == 0) ? 128 : (t3 == 1) ? 256 : 384;
        out[(size_t)b * 512 + off + tid] = c;
        __syncthreads();
    }
}

// ---------------------------------------------------------------------------
extern "C" void kernel_launch(void* const* d_in, const int* in_sizes, int n_in,
                              void* d_out, int out_size) {
    const int*   leaf_idx = (const int*)d_in[0];
    const int*   nf_ids   = (const int*)d_in[1];
    const int*   lf_ids   = (const int*)d_in[2];
    const int*   th_idx   = (const int*)d_in[3];
    const float* ent_emb  = (const float*)d_in[4];
    const float* th_emb   = (const float*)d_in[5];
    const float* nf_W1 = (const float*)d_in[6];
    const float* nf_b1 = (const float*)d_in[7];
    const float* nf_W2 = (const float*)d_in[8];
    const float* nf_b2 = (const float*)d_in[9];
    const float* lf_W1 = (const float*)d_in[10];
    const float* lf_b1 = (const float*)d_in[11];
    const float* lf_W2 = (const float*)d_in[12];
    const float* lf_b2 = (const float*)d_in[13];
    const float* he_W = (const float*)d_in[14];
    const float* he_b = (const float*)d_in[15];
    const float* hg_W = (const float*)d_in[16];
    const float* hg_b = (const float*)d_in[17];
    const float* ht_W = (const float*)d_in[18];
    const float* ht_b = (const float*)d_in[19];
    float* out = (float*)d_out;

    cudaFuncSetAttribute(nf_mma_kernel, cudaFuncAttributeMaxDynamicSharedMemorySize, NF_SMEM);
    cudaFuncSetAttribute(lf_gemm_kernel, cudaFuncAttributeMaxDynamicSharedMemorySize, LF_SMEM);

    zero_counts_kernel<<<1, 32>>>();
    compact_kernel<<<(L0N + L1N + L2N + L3N + LFN) / 256, 256>>>(nf_ids, lf_ids);
    prep_w_kernel<<<(4 * 16 * 4 * 256 + 4 * 16 * 2 * 256) / 256, 256>>>(nf_W1, nf_W2);

    // flat compacted grids: N/64 + 4 blocks (ceil-prefix slack)
    nf_mma_kernel<<<L0N / 64 + 4, 256, NF_SMEM>>>(0, leaf_idx, ent_emb, nf_b1, nf_b2);
    nf_mma_kernel<<<L1N / 64 + 4, 256, NF_SMEM>>>(1, leaf_idx, ent_emb, nf_b1, nf_b2);
    nf_mma_kernel<<<L2N / 64 + 4, 256, NF_SMEM>>>(2, leaf_idx, ent_emb, nf_b1, nf_b2);
    nf_mma_kernel<<<L3N / 64 + 4, 256, NF_SMEM>>>(3, leaf_idx, ent_emb, nf_b1, nf_b2);

    lf_gemm_kernel<<<dim3(LFN / TMLF, 3), 256, LF_SMEM>>>(lf_W1, lf_b1, lf_W2, lf_b2);

    attn_kernel<<<Bn, E>>>(th_idx, th_emb, he_W, he_b, hg_W, hg_b, ht_W, ht_b, out);
}